// round 10
// baseline (speedup 1.0000x reference)
#include <cuda_runtime.h>
#include <cuda_bf16.h>
#include <math.h>

#define B   512
#define TP  256
#define DM  512
#define DS  32
#define NE  6
#define NPAIR 532

// ---------------- device scratch ----------------
__device__ float g_ab[1000];
__device__ float g_gctx[B*DM];
__device__ float g_temb[B*DM];
__device__ float g_probs[B*NE];
__device__ int   g_sel[B];
__device__ float g_loss[B];
__device__ float g_outsub[NE*4*64*64];
__device__ int   g_cnt[NE];
__device__ int   g_list[NE*512];
__device__ float g_base[NE*B*512];
__device__ __nv_bfloat16 c_Wenc[DM*64];
__device__ __nv_bfloat16 c_W1n[NE*512*64];
__device__ __nv_bfloat16 c_W1b[(size_t)NE*512*1024];
__device__ __nv_bfloat16 c_W2t[NE*64*512];
__device__ float g_accL, g_accC, g_accS;
__device__ float g_psumE[NE];
__device__ float g_cntF[NE];
__device__ unsigned g_finDone;

__device__ __forceinline__ float gelu_fast(float x){
    float s = x*x;
    float p = x * fmaf(s, 0.044715f, 1.0f);
    float argv = p * -2.3022083f;
    float e;
    asm("ex2.approx.f32 %0, %1;" : "=f"(e) : "f"(argv));
    float r;
    asm("rcp.approx.f32 %0, %1;" : "=f"(r) : "f"(e + 1.0f));
    return x * r;
}

__device__ __forceinline__ void mma16816(float* c, const unsigned* a, unsigned b0, unsigned b1){
    asm("mma.sync.aligned.m16n8k16.row.col.f32.bf16.bf16.f32 "
        "{%0,%1,%2,%3}, {%4,%5,%6,%7}, {%8,%9}, {%0,%1,%2,%3};"
        : "+f"(c[0]), "+f"(c[1]), "+f"(c[2]), "+f"(c[3])
        : "r"(a[0]), "r"(a[1]), "r"(a[2]), "r"(a[3]), "r"(b0), "r"(b1));
}

// ---------------- K0: init scalars + Wenc convert ----------------
__global__ void k_init2(const float* __restrict__ Wenc){
    int tid = threadIdx.x;
    if (blockIdx.x == 0){
        if (tid < NE){ g_cnt[tid] = 0; g_psumE[tid] = 0.0f; g_cntF[tid] = 0.0f; }
        if (tid == 6){ g_accL = 0.0f; g_accC = 0.0f; g_accS = 0.0f; g_finDone = 0u; }
        g_loss[tid] = 0.0f;
        g_loss[tid + 256] = 0.0f;
        if (tid == 0){
            float ab = 1.0f;
            const float step = (0.02f - 0.0001f) / 999.0f;
            for (int i = 0; i < 1000; i++){
                float beta = 0.0001f + step * (float)i;
                ab *= (1.0f - beta);
                g_ab[i] = ab;
            }
        }
    } else {
        int gid = (blockIdx.x - 1)*256 + tid;
        int n = gid >> 1, kh = (gid & 1) * 32;
        #pragma unroll
        for (int i = 0; i < 32; i++){
            int k = kh + i;
            c_Wenc[n*64 + k] = __float2bfloat16_rn(Wenc[k*DM + n]);
        }
    }
}

// ---------------- K1: merged prep (W1, W2 converts + temb) ----------------
__global__ void k_prep(const int* __restrict__ t,
                       const float* __restrict__ W1, const float* __restrict__ W2){
    __shared__ float sm[32][33];
    int bid = blockIdx.x;
    int tid = threadIdx.x;

    if (bid < 3264){
        int e = bid / 544, rem = bid - e*544;
        int kt = rem >> 4, ht = rem & 15;
        int i = tid >> 3, j4 = (tid & 7) * 4;
        float4 v = *(const float4*)&W1[((size_t)e*1088 + kt*32 + i)*512 + ht*32 + j4];
        sm[i][j4] = v.x; sm[i][j4+1] = v.y; sm[i][j4+2] = v.z; sm[i][j4+3] = v.w;
        __syncthreads();
        int h = ht*32 + i;
        int k = kt*32 + j4;
        __nv_bfloat162 p0 = __floats2bfloat162_rn(sm[j4][i],   sm[j4+1][i]);
        __nv_bfloat162 p1 = __floats2bfloat162_rn(sm[j4+2][i], sm[j4+3][i]);
        __nv_bfloat16* dst;
        if (kt < 2) dst = c_W1n + ((size_t)e*512 + h)*64 + k;
        else        dst = c_W1b + ((size_t)e*512 + h)*1024 + (k - 64);
        *(__nv_bfloat162*)dst       = p0;
        *(__nv_bfloat162*)(dst + 2) = p1;
    } else if (bid < 3456){
        int idx2 = bid - 3264;
        int e = idx2 >> 5, rem = idx2 & 31;
        int ht = rem >> 1, ft = rem & 1;
        int i = tid >> 3, j4 = (tid & 7) * 4;
        float4 v = *(const float4*)&W2[((size_t)e*512 + ht*32 + i)*64 + ft*32 + j4];
        sm[i][j4] = v.x; sm[i][j4+1] = v.y; sm[i][j4+2] = v.z; sm[i][j4+3] = v.w;
        __syncthreads();
        int f = ft*32 + i;
        int h = ht*32 + j4;
        __nv_bfloat162 p0 = __floats2bfloat162_rn(sm[j4][i],   sm[j4+1][i]);
        __nv_bfloat162 p1 = __floats2bfloat162_rn(sm[j4+2][i], sm[j4+3][i]);
        __nv_bfloat16* dst = c_W2t + ((size_t)e*64 + f)*512 + h;
        *(__nv_bfloat162*)dst       = p0;
        *(__nv_bfloat162*)(dst + 2) = p1;
    } else {
        int b = bid - 3456;
        float tv = (float)t[b];
        for (int j = tid; j < DM; j += 256){
            int i = (j < 256) ? j : (j - 256);
            float freq = expf(-9.210340371976184f * (float)i / 256.0f);
            float a = tv * freq;
            g_temb[b*DM + j] = (j < 256) ? sinf(a) : cosf(a);
        }
    }
}

// ---------------- K2: fused ctx GEMM + router (validated R8) ----------------
#define APAD 72
__global__ void __launch_bounds__(512, 1)
k_ctx_fused(const float* __restrict__ obs, const float* __restrict__ sc,
            const float* __restrict__ benc, const float* __restrict__ Wstat,
            const float* __restrict__ Wr, const float* __restrict__ br,
            const int* __restrict__ phase){
    extern __shared__ char smraw[];
    __nv_bfloat16* As = (__nv_bfloat16*)smraw;
    float* pre  = (float*)(As + 256*APAD);
    float* gbuf = pre + 512;

    int b = blockIdx.x;
    int tid = threadIdx.x;

    {
        int row = tid >> 1;
        int c0  = (tid & 1) * 32;
        const float4* src = (const float4*)(obs + (size_t)b*TP*64 + row*64 + c0);
        __nv_bfloat16* arow = As + row*APAD + c0;
        #pragma unroll
        for (int i = 0; i < 8; i++){
            float4 v = src[i];
            *(__nv_bfloat162*)(arow + i*4    ) = __floats2bfloat162_rn(v.x, v.y);
            *(__nv_bfloat162*)(arow + i*4 + 2) = __floats2bfloat162_rn(v.z, v.w);
        }
    }
    {
        float acc = benc[tid];
        #pragma unroll
        for (int k = 0; k < 32; k++) acc = fmaf(sc[b*DS + k], Wstat[k*DM + tid], acc);
        pre[tid] = acc;
    }
    __syncthreads();

    int warp = tid >> 5, lane = tid & 31;
    int qrow = lane >> 2, qk2 = (lane & 3) * 2;
    int n0 = warp * 32;

    unsigned bfr[4][4][2];
    #pragma unroll
    for (int nt = 0; nt < 4; nt++)
        #pragma unroll
        for (int ks = 0; ks < 4; ks++){
            const __nv_bfloat16* bp = c_Wenc + (n0 + nt*8 + qrow)*64 + ks*16 + qk2;
            bfr[nt][ks][0] = *(const unsigned*)(bp);
            bfr[nt][ks][1] = *(const unsigned*)(bp + 8);
        }
    float prev[4][2];
    #pragma unroll
    for (int nt = 0; nt < 4; nt++){
        prev[nt][0] = pre[n0 + nt*8 + qk2];
        prev[nt][1] = pre[n0 + nt*8 + qk2 + 1];
    }

    float s[4][2];
    #pragma unroll
    for (int nt = 0; nt < 4; nt++){ s[nt][0] = 0.0f; s[nt][1] = 0.0f; }

    #pragma unroll 2
    for (int mc = 0; mc < 8; mc++){
        unsigned a[2][4][4];
        #pragma unroll
        for (int mt = 0; mt < 2; mt++)
            #pragma unroll
            for (int ks = 0; ks < 4; ks++){
                const __nv_bfloat16* ap = As + (mc*32 + mt*16 + qrow)*APAD + ks*16 + qk2;
                a[mt][ks][0] = *(const unsigned*)(ap);
                a[mt][ks][1] = *(const unsigned*)(ap + 8*APAD);
                a[mt][ks][2] = *(const unsigned*)(ap + 8);
                a[mt][ks][3] = *(const unsigned*)(ap + 8*APAD + 8);
            }
        float c[2][4][4];
        #pragma unroll
        for (int mt = 0; mt < 2; mt++)
            #pragma unroll
            for (int nt = 0; nt < 4; nt++)
                #pragma unroll
                for (int r = 0; r < 4; r++) c[mt][nt][r] = 0.0f;
        #pragma unroll
        for (int ks = 0; ks < 4; ks++)
            #pragma unroll
            for (int mt = 0; mt < 2; mt++)
                #pragma unroll
                for (int nt = 0; nt < 4; nt++)
                    mma16816(c[mt][nt], a[mt][ks], bfr[nt][ks][0], bfr[nt][ks][1]);
        #pragma unroll
        for (int mt = 0; mt < 2; mt++)
            #pragma unroll
            for (int nt = 0; nt < 4; nt++){
                s[nt][0] += gelu_fast(c[mt][nt][0] + prev[nt][0]) + gelu_fast(c[mt][nt][2] + prev[nt][0]);
                s[nt][1] += gelu_fast(c[mt][nt][1] + prev[nt][1]) + gelu_fast(c[mt][nt][3] + prev[nt][1]);
            }
    }

    #pragma unroll
    for (int off = 16; off >= 4; off >>= 1)
        #pragma unroll
        for (int nt = 0; nt < 4; nt++){
            s[nt][0] += __shfl_xor_sync(0xffffffff, s[nt][0], off);
            s[nt][1] += __shfl_xor_sync(0xffffffff, s[nt][1], off);
        }
    if (qrow == 0){
        #pragma unroll
        for (int nt = 0; nt < 4; nt++){
            int j = n0 + nt*8 + qk2;
            float v0 = s[nt][0] * (1.0f/256.0f);
            float v1 = s[nt][1] * (1.0f/256.0f);
            gbuf[j] = v0; gbuf[j+1] = v1;
            g_gctx[b*DM + j]     = v0;
            g_gctx[b*DM + j + 1] = v1;
        }
    }
    __syncthreads();

    if (warp == 0){
        float p[6] = {0,0,0,0,0,0};
        for (int k = lane; k < DM; k += 32){
            float g = gbuf[k];
            const float* w = Wr + k*NE;
            #pragma unroll
            for (int e = 0; e < 6; e++) p[e] = fmaf(g, w[e], p[e]);
        }
        #pragma unroll
        for (int off = 16; off; off >>= 1)
            #pragma unroll
            for (int e = 0; e < 6; e++) p[e] += __shfl_xor_sync(0xffffffff, p[e], off);
        if (lane == 0){
            float l[6], pr[6];
            #pragma unroll
            for (int e = 0; e < 6; e++) l[e] = p[e] + br[e];
            float m = l[0];
            #pragma unroll
            for (int e = 1; e < 6; e++) m = fmaxf(m, l[e]);
            float sv = 0.0f;
            #pragma unroll
            for (int e = 0; e < 6; e++){ pr[e] = expf(l[e] - m); sv += pr[e]; }
            float inv = 1.0f / sv;
            #pragma unroll
            for (int e = 0; e < 6; e++){ pr[e] *= inv; g_probs[b*NE + e] = pr[e]; }
            int pl = phase[b];
            int sel = pl + ((pr[pl+3] > pr[pl]) ? 3 : 0);
            g_sel[b] = sel;
            if (b < 4){
                #pragma unroll
                for (int e = 0; e < 6; e++){
                    int idx = atomicAdd(&g_cnt[e], 1);
                    g_list[e*512 + idx] = b;
                }
            } else {
                int idx = atomicAdd(&g_cnt[sel], 1);
                g_list[sel*512 + idx] = b;
            }
        }
    }
}

// ---------------- K3c: base via bf16 MMA, 16 warps, 16 cols/warp ----------------
__global__ void __launch_bounds__(512, 1)
k_base(const float* __restrict__ b1){
    extern __shared__ char smraw[];
    __nv_bfloat16* As = (__nv_bfloat16*)smraw;   // 32 x 1032
    int* bl = (int*)(As + 32*1032);              // 32

    int e = blockIdx.x, tile = blockIdx.y;
    int n = g_cnt[e], s0 = tile*32;
    if (s0 >= n) return;
    int tid = threadIdx.x;

    if (tid < 32){
        int s = s0 + tid;
        bl[tid] = (s < n) ? g_list[e*512 + s] : g_list[e*512];
    }
    __syncthreads();

    {   // fill As: 32 rows x 1024 cols bf16, 512 threads
        int r = tid >> 4, seg = tid & 15;
        int bb = bl[r];
        const float4* src = (const float4*)((seg < 8)
            ? (g_gctx + bb*512 + seg*64)
            : (g_temb + bb*512 + (seg - 8)*64));
        __nv_bfloat16* dst = As + r*1032 + seg*64;
        #pragma unroll
        for (int i = 0; i < 16; i++){
            float4 v = src[i];
            *(__nv_bfloat162*)(dst + i*4    ) = __floats2bfloat162_rn(v.x, v.y);
            *(__nv_bfloat162*)(dst + i*4 + 2) = __floats2bfloat162_rn(v.z, v.w);
        }
    }
    __syncthreads();

    int warp = tid >> 5, lane = tid & 31;
    int qrow = lane >> 2;
    int qk2 = (lane & 3) * 2;
    int nb = blockIdx.z * 256 + warp * 16;
    const __nv_bfloat16* W1bE = c_W1b + (size_t)e*512*1024;

    float acc[2][2][4];
    #pragma unroll
    for (int mt = 0; mt < 2; mt++)
        #pragma unroll
        for (int nt = 0; nt < 2; nt++)
            #pragma unroll
            for (int r = 0; r < 4; r++) acc[mt][nt][r] = 0.0f;

    for (int kc = 0; kc < 16; kc++){
        #pragma unroll
        for (int ks = 0; ks < 4; ks++){
            int kof = kc*64 + ks*16 + qk2;
            unsigned a[2][4];
            #pragma unroll
            for (int mt = 0; mt < 2; mt++){
                const __nv_bfloat16* ap = As + (mt*16 + qrow)*1032 + kof;
                a[mt][0] = *(const unsigned*)(ap);
                a[mt][1] = *(const unsigned*)(ap + 8*1032);
                a[mt][2] = *(const unsigned*)(ap + 8);
                a[mt][3] = *(const unsigned*)(ap + 8*1032 + 8);
            }
            #pragma unroll
            for (int nt = 0; nt < 2; nt++){
                const __nv_bfloat16* bp = W1bE + (size_t)(nb + nt*8 + qrow)*1024 + kof;
                unsigned b0 = *(const unsigned*)(bp);
                unsigned b1v = *(const unsigned*)(bp + 8);
                mma16816(acc[0][nt], a[0], b0, b1v);
                mma16816(acc[1][nt], a[1], b0, b1v);
            }
        }
    }

    #pragma unroll
    for (int mt = 0; mt < 2; mt++){
        #pragma unroll
        for (int half = 0; half < 2; half++){
            int r = mt*16 + qrow + half*8;
            if (s0 + r < n){
                int bb = bl[r];
                float* dst = g_base + ((size_t)e*B + bb)*512;
                #pragma unroll
                for (int nt = 0; nt < 2; nt++){
                    int h = nb + nt*8 + qk2;
                    float2 o;
                    o.x = acc[mt][nt][half*2    ] + b1[e*512 + h];
                    o.y = acc[mt][nt][half*2 + 1] + b1[e*512 + h + 1];
                    *(float2*)(dst + h) = o;
                }
            }
        }
    }
}

// ---------------- K4: expert MLP, M-split quarters, 128 threads ----------------
__global__ void __launch_bounds__(128, 8)
k_expert(const float* __restrict__ fut, const float* __restrict__ eps,
         const int* __restrict__ t, const float* __restrict__ b2){
    extern __shared__ char smraw[];
    __nv_bfloat16* nzs = (__nv_bfloat16*)smraw;       // 16 x 72
    __nv_bfloat16* hss = nzs + 16*72;                 // 16 x 520
    float* basev = (float*)(hss + 16*520);            // 512
    __shared__ float red[4];

    int p4 = blockIdx.x;
    int p = p4 >> 2, mq = p4 & 3;
    int b, e;
    if (p < 24){ b = p / 6; e = p - b*6; }
    else       { b = p - 20; e = g_sel[p - 20]; }
    int tid = threadIdx.x;
    bool do_loss  = (e == g_sel[b]);
    bool do_store = (b < 4);

    float ab = g_ab[t[b]];
    float sa = sqrtf(ab), sb = sqrtf(1.0f - ab);

    {   // nzs = bf16(noisy) rows [mq*16, mq*16+16)
        int r = tid >> 3, c0 = (tid & 7) * 8;
        int gr = mq*16 + r;
        const float4* f4 = (const float4*)(fut + (size_t)b*4096 + gr*64 + c0);
        const float4* e4 = (const float4*)(eps + (size_t)b*4096 + gr*64 + c0);
        __nv_bfloat16* dst = nzs + r*72 + c0;
        #pragma unroll
        for (int i = 0; i < 2; i++){
            float4 vf = f4[i], ve = e4[i];
            *(__nv_bfloat162*)(dst + i*4    ) = __floats2bfloat162_rn(fmaf(sa,vf.x,sb*ve.x), fmaf(sa,vf.y,sb*ve.y));
            *(__nv_bfloat162*)(dst + i*4 + 2) = __floats2bfloat162_rn(fmaf(sa,vf.z,sb*ve.z), fmaf(sa,vf.w,sb*ve.w));
        }
    }
    #pragma unroll
    for (int i = 0; i < 4; i++)
        basev[tid + i*128] = g_base[((size_t)e*B + b)*512 + tid + i*128];
    __syncthreads();

    int warp = tid >> 5, lane = tid & 31;
    int qrow = lane >> 2, qk2 = (lane & 3) * 2;

    // ---- phase1: warp owns 128 h-cols, M=16 local ----
    {
        int n0 = warp * 128;
        const __nv_bfloat16* W1nE = c_W1n + (size_t)e*512*64;

        unsigned a[4][4];
        #pragma unroll
        for (int ks = 0; ks < 4; ks++){
            const __nv_bfloat16* ap = nzs + qrow*72 + ks*16 + qk2;
            a[ks][0] = *(const unsigned*)(ap);
            a[ks][1] = *(const unsigned*)(ap + 8*72);
            a[ks][2] = *(const unsigned*)(ap + 8);
            a[ks][3] = *(const unsigned*)(ap + 8*72 + 8);
        }

        #pragma unroll 4
        for (int nto = 0; nto < 16; nto++){
            int h8 = n0 + nto*8;
            unsigned bfr[4][2];
            #pragma unroll
            for (int ks = 0; ks < 4; ks++){
                const __nv_bfloat16* bp = W1nE + (h8 + qrow)*64 + ks*16 + qk2;
                bfr[ks][0] = *(const unsigned*)(bp);
                bfr[ks][1] = *(const unsigned*)(bp + 8);
            }
            float c0v[4] = {0.0f, 0.0f, 0.0f, 0.0f};
            #pragma unroll
            for (int ks = 0; ks < 4; ks++)
                mma16816(c0v, a[ks], bfr[ks][0], bfr[ks][1]);
            int h = h8 + qk2;
            float ba0 = basev[h], ba1 = basev[h+1];
            *(__nv_bfloat162*)(hss + qrow*520 + h) =
                __floats2bfloat162_rn(gelu_fast(c0v[0] + ba0), gelu_fast(c0v[1] + ba1));
            *(__nv_bfloat162*)(hss + (qrow+8)*520 + h) =
                __floats2bfloat162_rn(gelu_fast(c0v[2] + ba0), gelu_fast(c0v[3] + ba1));
        }
    }
    __syncthreads();

    // ---- phase2: warp owns 16 f-cols, M=16 local, K=512 ----
    int f0 = warp * 16;
    const __nv_bfloat16* W2tE = c_W2t + (size_t)e*64*512;

    float acc[2][4];
    #pragma unroll
    for (int nt = 0; nt < 2; nt++)
        #pragma unroll
        for (int r = 0; r < 4; r++) acc[nt][r] = 0.0f;

    #pragma unroll 8
    for (int ks = 0; ks < 32; ks++){
        unsigned bfr[2][2];
        #pragma unroll
        for (int nt = 0; nt < 2; nt++){
            const __nv_bfloat16* bp = W2tE + (f0 + nt*8 + qrow)*512 + ks*16 + qk2;
            bfr[nt][0] = *(const unsigned*)(bp);
            bfr[nt][1] = *(const unsigned*)(bp + 8);
        }
        const __nv_bfloat16* ap = hss + qrow*520 + ks*16 + qk2;
        unsigned a2[4];
        a2[0] = *(const unsigned*)(ap);
        a2[1] = *(const unsigned*)(ap + 8*520);
        a2[2] = *(const unsigned*)(ap + 8);
        a2[3] = *(const unsigned*)(ap + 8*520 + 8);
        mma16816(acc[0], a2, bfr[0][0], bfr[0][1]);
        mma16816(acc[1], a2, bfr[1][0], bfr[1][1]);
    }

    float lsum = 0.0f;
    #pragma unroll
    for (int nt = 0; nt < 2; nt++){
        int fcol = f0 + nt*8 + qk2;
        float bb0 = b2[e*64 + fcol], bb1 = b2[e*64 + fcol + 1];
        #pragma unroll
        for (int h2 = 0; h2 < 2; h2++){
            int rg = mq*16 + qrow + h2*8;
            float o0 = acc[nt][h2*2    ] + bb0;
            float o1 = acc[nt][h2*2 + 1] + bb1;
            if (do_store){
                float2 st; st.x = o0; st.y = o1;
                *(float2*)&g_outsub[((e*4 + b)*64 + rg)*64 + fcol] = st;
            }
            if (do_loss){
                float2 ev = *(const float2*)&eps[(size_t)b*4096 + rg*64 + fcol];
                float d0 = o0 - ev.x, d1 = o1 - ev.y;
                lsum += d0*d0 + d1*d1;
            }
        }
    }

    if (do_loss){
        #pragma unroll
        for (int off = 16; off; off >>= 1) lsum += __shfl_xor_sync(0xffffffff, lsum, off);
        if (lane == 0) red[warp] = lsum;
        __syncthreads();
        if (tid == 0){
            float tot = red[0] + red[1] + red[2] + red[3];
            atomicAdd(&g_loss[b], tot * (1.0f/4096.0f));
        }
    }
}

// ---------------- K5: parallel final reduction + last-block scalar ----------------
#define FIN_BLKS 96
__global__ void k_final(float* __restrict__ out){
    int bid = blockIdx.x, tid = threadIdx.x;
    if (bid < 2){
        __shared__ float sh[13];
        if (tid < 13) sh[tid] = 0.0f;
        __syncthreads();
        const float PW[3] = {1.0f, 5.0f, 5.0f};
        int b = bid*256 + tid;
        int s = g_sel[b];
        atomicAdd(&sh[0], g_loss[b] * PW[s % 3]);
        atomicAdd(&sh[1 + s], 1.0f);
        #pragma unroll
        for (int e = 0; e < 6; e++) atomicAdd(&sh[7 + e], g_probs[b*NE + e]);
        __syncthreads();
        if (tid == 0) atomicAdd(&g_accL, sh[0]);
        if (tid < 6){
            atomicAdd(&g_cntF[tid],  sh[1 + tid]);
            atomicAdd(&g_psumE[tid], sh[7 + tid]);
        }
    } else {
        int nb = FIN_BLKS - 2;
        int idx0 = (bid - 2)*256 + tid;
        int stride = nb*256;
        const int pa[7] = {0,1,3,4,0,1,2};
        const int pb[7] = {1,2,4,5,3,4,5};
        float ch = 0.0f;
        for (int i = idx0; i < 16384; i += stride){
            #pragma unroll
            for (int q = 0; q < 7; q++){
                float d = g_outsub[pa[q]*16384 + i] - g_outsub[pb[q]*16384 + i];
                ch += d*d;
            }
        }
        float smv = 0.0f;
        for (int i = idx0; i < 96768; i += stride){
            int e  = i / 16128; int r  = i - e*16128;
            int s  = r / 4032;  int r2 = r - s*4032;
            int idx = (e*4 + s)*4096 + r2;
            float d = g_outsub[idx + 64] - g_outsub[idx];
            smv += d*d;
        }
        #pragma unroll
        for (int off = 16; off; off >>= 1){
            ch  += __shfl_xor_sync(0xffffffff, ch,  off);
            smv += __shfl_xor_sync(0xffffffff, smv, off);
        }
        if ((tid & 31) == 0){
            atomicAdd(&g_accC, ch);
            atomicAdd(&g_accS, smv);
        }
    }

    __syncthreads();
    __shared__ bool amLast;
    if (tid == 0){
        __threadfence();
        unsigned old = atomicAdd(&g_finDone, 1u);
        amLast = (old == FIN_BLKS - 1);
    }
    __syncthreads();
    if (amLast && tid == 0){
        __threadfence();
        float lb = 0.0f;
        #pragma unroll
        for (int e = 0; e < 6; e++)
            lb += (g_cntF[e] / 512.0f) * (g_psumE[e] / 512.0f);
        out[0] = g_accL / 512.0f
               + 0.01f * (g_accC / 16384.0f + 0.5f * g_accS / 16128.0f)
               + 0.06f * lb;
    }
}

// ---------------- launch ----------------
extern "C" void kernel_launch(void* const* d_in, const int* in_sizes, int n_in,
                              void* d_out, int out_size){
    const float* obs  = (const float*)d_in[0];
    const float* fut  = (const float*)d_in[1];
    const float* sc   = (const float*)d_in[2];
    const float* eps  = (const float*)d_in[3];
    const int*   phase= (const int*)  d_in[4];
    const int*   t    = (const int*)  d_in[5];
    const float* Wenc = (const float*)d_in[6];
    const float* benc = (const float*)d_in[7];
    const float* Wstat= (const float*)d_in[8];
    const float* Wr   = (const float*)d_in[9];
    const float* br   = (const float*)d_in[10];
    const float* W1   = (const float*)d_in[11];
    const float* b1   = (const float*)d_in[12];
    const float* W2   = (const float*)d_in[13];
    const float* b2   = (const float*)d_in[14];

    const int SMEM_CTX  = 256*APAD*2 + 2*512*4;            // 40,960 B
    const int SMEM_BASE = 32*1032*2 + 128;                 // 66,176 B
    const int SMEM_EXP  = (16*72 + 16*520)*2 + 512*4;      // 20,992 B

    static bool once = false;
    static cudaStream_t s2;
    static cudaEvent_t evFork, evJoin;
    if (!once){
        cudaFuncSetAttribute(k_ctx_fused, cudaFuncAttributeMaxDynamicSharedMemorySize, SMEM_CTX);
        cudaFuncSetAttribute(k_base,      cudaFuncAttributeMaxDynamicSharedMemorySize, SMEM_BASE);
        cudaFuncSetAttribute(k_expert,    cudaFuncAttributeMaxDynamicSharedMemorySize, SMEM_EXP);
        cudaStreamCreateWithFlags(&s2, cudaStreamNonBlocking);
        cudaEventCreateWithFlags(&evFork, cudaEventDisableTiming);
        cudaEventCreateWithFlags(&evJoin, cudaEventDisableTiming);
        once = true;
    }

    k_init2<<<5, 256>>>(Wenc);

    cudaEventRecord(evFork, 0);
    cudaStreamWaitEvent(s2, evFork, 0);
    k_prep<<<3968, 256, 0, s2>>>(t, W1, W2);
    cudaEventRecord(evJoin, s2);

    k_ctx_fused<<<B, 512, SMEM_CTX>>>(obs, sc, benc, Wstat, Wr, br, phase);

    cudaStreamWaitEvent(0, evJoin, 0);

    k_base  <<<dim3(NE, 16, 2), 512, SMEM_BASE>>>(b1);
    k_expert<<<4*NPAIR, 128, SMEM_EXP>>>(fut, eps, t, b2);
    k_final <<<FIN_BLKS, 256>>>((float*)d_out);
}

// round 12
// speedup vs baseline: 1.2747x; 1.2747x over previous
#include <cuda_runtime.h>
#include <cuda_bf16.h>
#include <math.h>

#define B   512
#define TP  256
#define DM  512
#define DS  32
#define NE  6
#define NPAIR 532

// ---------------- device scratch ----------------
__device__ float g_ab[1000];
__device__ float g_gctx[B*DM];
__device__ float g_temb[B*DM];
__device__ float g_probs[B*NE];
__device__ int   g_sel[B];
__device__ float g_loss[B];
__device__ float g_outsub[NE*4*64*64];
__device__ int   g_cnt[NE];
__device__ int   g_list[NE*512];
__device__ float g_base[NE*B*512];
// fragment-tiled bf16 weights: each n8 x k16 tile contiguous as [r(8)][kk(16)] = 128 elems
__device__ __nv_bfloat16 c_Wenc[DM*64];                 // [ng 64][kg 4][128]
__device__ __nv_bfloat16 c_W1n[NE*512*64];              // [e][hg 64][kg 4][128]
__device__ __nv_bfloat16 c_W1b[(size_t)NE*512*1024];    // [e][hg 64][kg 64][128]
__device__ __nv_bfloat16 c_W2t[NE*64*512];              // [e][fg 8][kg 32][128]
__device__ float g_accL, g_accC, g_accS;
__device__ float g_psumE[NE];
__device__ float g_cntF[NE];
__device__ unsigned g_finDone;

__device__ __forceinline__ float gelu_fast(float x){
    float s = x*x;
    float p = x * fmaf(s, 0.044715f, 1.0f);
    float argv = p * -2.3022083f;
    float e;
    asm("ex2.approx.f32 %0, %1;" : "=f"(e) : "f"(argv));
    float r;
    asm("rcp.approx.f32 %0, %1;" : "=f"(r) : "f"(e + 1.0f));
    return x * r;
}

__device__ __forceinline__ void mma16816(float* c, const unsigned* a, unsigned b0, unsigned b1){
    asm("mma.sync.aligned.m16n8k16.row.col.f32.bf16.bf16.f32 "
        "{%0,%1,%2,%3}, {%4,%5,%6,%7}, {%8,%9}, {%0,%1,%2,%3};"
        : "+f"(c[0]), "+f"(c[1]), "+f"(c[2]), "+f"(c[3])
        : "r"(a[0]), "r"(a[1]), "r"(a[2]), "r"(a[3]), "r"(b0), "r"(b1));
}

// ---------------- K0: init scalars + Wenc convert (tiled) ----------------
__global__ void k_init2(const float* __restrict__ Wenc){
    int tid = threadIdx.x;
    if (blockIdx.x == 0){
        if (tid < NE){ g_cnt[tid] = 0; g_psumE[tid] = 0.0f; g_cntF[tid] = 0.0f; }
        if (tid == 6){ g_accL = 0.0f; g_accC = 0.0f; g_accS = 0.0f; g_finDone = 0u; }
        g_loss[tid] = 0.0f;
        g_loss[tid + 256] = 0.0f;
        if (tid == 0){
            float ab = 1.0f;
            const float step = (0.02f - 0.0001f) / 999.0f;
            for (int i = 0; i < 1000; i++){
                float beta = 0.0001f + step * (float)i;
                ab *= (1.0f - beta);
                g_ab[i] = ab;
            }
        }
    } else {
        int gid = (blockIdx.x - 1)*256 + tid;   // 1024 threads
        int n = gid >> 1, kh = (gid & 1) * 32;
        int ng = n >> 3, r = n & 7;
        #pragma unroll
        for (int i = 0; i < 32; i++){
            int k = kh + i;
            int kg = k >> 4, kk = k & 15;
            c_Wenc[(ng*4 + kg)*128 + r*16 + kk] = __float2bfloat16_rn(Wenc[k*DM + n]);
        }
    }
}

// ---------------- K1: merged prep (W1, W2 converts + temb), tiled writes ----------------
__global__ void k_prep(const int* __restrict__ t,
                       const float* __restrict__ W1, const float* __restrict__ W2){
    __shared__ float sm[32][33];
    int bid = blockIdx.x;
    int tid = threadIdx.x;

    if (bid < 3264){                       // W1 convert
        int e = bid / 544, rem = bid - e*544;
        int kt = rem >> 4, ht = rem & 15;
        int i = tid >> 3, j4 = (tid & 7) * 4;
        float4 v = *(const float4*)&W1[((size_t)e*1088 + kt*32 + i)*512 + ht*32 + j4];
        sm[i][j4] = v.x; sm[i][j4+1] = v.y; sm[i][j4+2] = v.z; sm[i][j4+3] = v.w;
        __syncthreads();
        int h = ht*32 + i;
        int k = kt*32 + j4;
        __nv_bfloat162 p0 = __floats2bfloat162_rn(sm[j4][i],   sm[j4+1][i]);
        __nv_bfloat162 p1 = __floats2bfloat162_rn(sm[j4+2][i], sm[j4+3][i]);
        int hg = h >> 3, r = h & 7;
        __nv_bfloat16* dst;
        if (kt < 2){
            int kg = k >> 4, kk = k & 15;
            dst = c_W1n + (size_t)e*32768 + (hg*4 + kg)*128 + r*16 + kk;
        } else {
            int kp = k - 64;
            int kg = kp >> 4, kk = kp & 15;
            dst = c_W1b + (size_t)e*524288 + (size_t)(hg*64 + kg)*128 + r*16 + kk;
        }
        *(__nv_bfloat162*)dst       = p0;
        *(__nv_bfloat162*)(dst + 2) = p1;
    } else if (bid < 3456){                // W2 convert
        int idx2 = bid - 3264;
        int e = idx2 >> 5, rem = idx2 & 31;
        int ht = rem >> 1, ft = rem & 1;
        int i = tid >> 3, j4 = (tid & 7) * 4;
        float4 v = *(const float4*)&W2[((size_t)e*512 + ht*32 + i)*64 + ft*32 + j4];
        sm[i][j4] = v.x; sm[i][j4+1] = v.y; sm[i][j4+2] = v.z; sm[i][j4+3] = v.w;
        __syncthreads();
        int f = ft*32 + i;
        int h = ht*32 + j4;
        __nv_bfloat162 p0 = __floats2bfloat162_rn(sm[j4][i],   sm[j4+1][i]);
        __nv_bfloat162 p1 = __floats2bfloat162_rn(sm[j4+2][i], sm[j4+3][i]);
        int fg = f >> 3, r = f & 7;
        int kg = h >> 4, kk = h & 15;
        __nv_bfloat16* dst = c_W2t + (size_t)e*32768 + (fg*32 + kg)*128 + r*16 + kk;
        *(__nv_bfloat162*)dst       = p0;
        *(__nv_bfloat162*)(dst + 2) = p1;
    } else {                               // temb
        int b = bid - 3456;
        float tv = (float)t[b];
        for (int j = tid; j < DM; j += 256){
            int i = (j < 256) ? j : (j - 256);
            float freq = expf(-9.210340371976184f * (float)i / 256.0f);
            float a = tv * freq;
            g_temb[b*DM + j] = (j < 256) ? sinf(a) : cosf(a);
        }
    }
}

// ---------------- K2: fused ctx GEMM + router ----------------
#define APAD 72
__global__ void __launch_bounds__(512, 1)
k_ctx_fused(const float* __restrict__ obs, const float* __restrict__ sc,
            const float* __restrict__ benc, const float* __restrict__ Wstat,
            const float* __restrict__ Wr, const float* __restrict__ br,
            const int* __restrict__ phase){
    extern __shared__ char smraw[];
    __nv_bfloat16* As = (__nv_bfloat16*)smraw;
    float* pre  = (float*)(As + 256*APAD);
    float* gbuf = pre + 512;

    int b = blockIdx.x;
    int tid = threadIdx.x;

    {
        int row = tid >> 1;
        int c0  = (tid & 1) * 32;
        const float4* src = (const float4*)(obs + (size_t)b*TP*64 + row*64 + c0);
        __nv_bfloat16* arow = As + row*APAD + c0;
        #pragma unroll
        for (int i = 0; i < 8; i++){
            float4 v = src[i];
            *(__nv_bfloat162*)(arow + i*4    ) = __floats2bfloat162_rn(v.x, v.y);
            *(__nv_bfloat162*)(arow + i*4 + 2) = __floats2bfloat162_rn(v.z, v.w);
        }
    }
    {
        float acc = benc[tid];
        #pragma unroll
        for (int k = 0; k < 32; k++) acc = fmaf(sc[b*DS + k], Wstat[k*DM + tid], acc);
        pre[tid] = acc;
    }
    __syncthreads();

    int warp = tid >> 5, lane = tid & 31;
    int qrow = lane >> 2, qk2 = (lane & 3) * 2;
    int n0 = warp * 32;

    // B fragments from tiled c_Wenc: ng = warp*4 + nt, kg = ks
    unsigned bfr[4][4][2];
    #pragma unroll
    for (int nt = 0; nt < 4; nt++)
        #pragma unroll
        for (int ks = 0; ks < 4; ks++){
            const __nv_bfloat16* bp = c_Wenc + ((warp*4 + nt)*4 + ks)*128 + qrow*16 + qk2;
            bfr[nt][ks][0] = *(const unsigned*)(bp);
            bfr[nt][ks][1] = *(const unsigned*)(bp + 8);
        }
    float prev[4][2];
    #pragma unroll
    for (int nt = 0; nt < 4; nt++){
        prev[nt][0] = pre[n0 + nt*8 + qk2];
        prev[nt][1] = pre[n0 + nt*8 + qk2 + 1];
    }

    float s[4][2];
    #pragma unroll
    for (int nt = 0; nt < 4; nt++){ s[nt][0] = 0.0f; s[nt][1] = 0.0f; }

    #pragma unroll 2
    for (int mc = 0; mc < 8; mc++){
        unsigned a[2][4][4];
        #pragma unroll
        for (int mt = 0; mt < 2; mt++)
            #pragma unroll
            for (int ks = 0; ks < 4; ks++){
                const __nv_bfloat16* ap = As + (mc*32 + mt*16 + qrow)*APAD + ks*16 + qk2;
                a[mt][ks][0] = *(const unsigned*)(ap);
                a[mt][ks][1] = *(const unsigned*)(ap + 8*APAD);
                a[mt][ks][2] = *(const unsigned*)(ap + 8);
                a[mt][ks][3] = *(const unsigned*)(ap + 8*APAD + 8);
            }
        float c[2][4][4];
        #pragma unroll
        for (int mt = 0; mt < 2; mt++)
            #pragma unroll
            for (int nt = 0; nt < 4; nt++)
                #pragma unroll
                for (int r = 0; r < 4; r++) c[mt][nt][r] = 0.0f;
        #pragma unroll
        for (int ks = 0; ks < 4; ks++)
            #pragma unroll
            for (int mt = 0; mt < 2; mt++)
                #pragma unroll
                for (int nt = 0; nt < 4; nt++)
                    mma16816(c[mt][nt], a[mt][ks], bfr[nt][ks][0], bfr[nt][ks][1]);
        #pragma unroll
        for (int mt = 0; mt < 2; mt++)
            #pragma unroll
            for (int nt = 0; nt < 4; nt++){
                s[nt][0] += gelu_fast(c[mt][nt][0] + prev[nt][0]) + gelu_fast(c[mt][nt][2] + prev[nt][0]);
                s[nt][1] += gelu_fast(c[mt][nt][1] + prev[nt][1]) + gelu_fast(c[mt][nt][3] + prev[nt][1]);
            }
    }

    #pragma unroll
    for (int off = 16; off >= 4; off >>= 1)
        #pragma unroll
        for (int nt = 0; nt < 4; nt++){
            s[nt][0] += __shfl_xor_sync(0xffffffff, s[nt][0], off);
            s[nt][1] += __shfl_xor_sync(0xffffffff, s[nt][1], off);
        }
    if (qrow == 0){
        #pragma unroll
        for (int nt = 0; nt < 4; nt++){
            int j = n0 + nt*8 + qk2;
            float v0 = s[nt][0] * (1.0f/256.0f);
            float v1 = s[nt][1] * (1.0f/256.0f);
            gbuf[j] = v0; gbuf[j+1] = v1;
            g_gctx[b*DM + j]     = v0;
            g_gctx[b*DM + j + 1] = v1;
        }
    }
    __syncthreads();

    if (warp == 0){
        float p[6] = {0,0,0,0,0,0};
        for (int k = lane; k < DM; k += 32){
            float g = gbuf[k];
            const float* w = Wr + k*NE;
            #pragma unroll
            for (int e = 0; e < 6; e++) p[e] = fmaf(g, w[e], p[e]);
        }
        #pragma unroll
        for (int off = 16; off; off >>= 1)
            #pragma unroll
            for (int e = 0; e < 6; e++) p[e] += __shfl_xor_sync(0xffffffff, p[e], off);
        if (lane == 0){
            float l[6], pr[6];
            #pragma unroll
            for (int e = 0; e < 6; e++) l[e] = p[e] + br[e];
            float m = l[0];
            #pragma unroll
            for (int e = 1; e < 6; e++) m = fmaxf(m, l[e]);
            float sv = 0.0f;
            #pragma unroll
            for (int e = 0; e < 6; e++){ pr[e] = expf(l[e] - m); sv += pr[e]; }
            float inv = 1.0f / sv;
            #pragma unroll
            for (int e = 0; e < 6; e++){ pr[e] *= inv; g_probs[b*NE + e] = pr[e]; }
            int pl = phase[b];
            int sel = pl + ((pr[pl+3] > pr[pl]) ? 3 : 0);
            g_sel[b] = sel;
            if (b < 4){
                #pragma unroll
                for (int e = 0; e < 6; e++){
                    int idx = atomicAdd(&g_cnt[e], 1);
                    g_list[e*512 + idx] = b;
                }
            } else {
                int idx = atomicAdd(&g_cnt[sel], 1);
                g_list[sel*512 + idx] = b;
            }
        }
    }
}

// ---------------- K3c: base via bf16 MMA (R9 shape, tiled B loads) ----------------
__global__ void __launch_bounds__(256, 1)
k_base(const float* __restrict__ b1){
    extern __shared__ char smraw[];
    __nv_bfloat16* As = (__nv_bfloat16*)smraw;   // 32 x 1032
    int* bl = (int*)(As + 32*1032);              // 32

    int e = blockIdx.x, tile = blockIdx.y;
    int n = g_cnt[e], s0 = tile*32;
    if (s0 >= n) return;
    int tid = threadIdx.x;

    if (tid < 32){
        int s = s0 + tid;
        bl[tid] = (s < n) ? g_list[e*512 + s] : g_list[e*512];
    }
    __syncthreads();

    {
        int r = tid >> 3, seg = tid & 7;
        int bb = bl[r];
        const float4* src = (const float4*)((seg < 4)
            ? (g_gctx + bb*512 + seg*128)
            : (g_temb + bb*512 + seg*128 - 512));
        __nv_bfloat16* dst = As + r*1032 + seg*128;
        #pragma unroll
        for (int i = 0; i < 32; i++){
            float4 v = src[i];
            *(__nv_bfloat162*)(dst + i*4    ) = __floats2bfloat162_rn(v.x, v.y);
            *(__nv_bfloat162*)(dst + i*4 + 2) = __floats2bfloat162_rn(v.z, v.w);
        }
    }
    __syncthreads();

    int warp = tid >> 5, lane = tid & 31;
    int qrow = lane >> 2;
    int qk2 = (lane & 3) * 2;
    int nb = blockIdx.z * 256 + warp * 32;
    int hg0 = nb >> 3;
    const __nv_bfloat16* W1bE = c_W1b + (size_t)e*524288;

    float acc[2][4][4];
    #pragma unroll
    for (int mt = 0; mt < 2; mt++)
        #pragma unroll
        for (int nt = 0; nt < 4; nt++)
            #pragma unroll
            for (int r = 0; r < 4; r++) acc[mt][nt][r] = 0.0f;

    for (int kc = 0; kc < 16; kc++){
        #pragma unroll
        for (int ks = 0; ks < 4; ks++){
            int kof = kc*64 + ks*16 + qk2;
            int kg = kc*4 + ks;
            unsigned a[2][4];
            #pragma unroll
            for (int mt = 0; mt < 2; mt++){
                const __nv_bfloat16* ap = As + (mt*16 + qrow)*1032 + kof;
                a[mt][0] = *(const unsigned*)(ap);
                a[mt][1] = *(const unsigned*)(ap + 8*1032);
                a[mt][2] = *(const unsigned*)(ap + 8);
                a[mt][3] = *(const unsigned*)(ap + 8*1032 + 8);
            }
            #pragma unroll
            for (int nt = 0; nt < 4; nt++){
                const __nv_bfloat16* bp = W1bE + (size_t)((hg0 + nt)*64 + kg)*128 + qrow*16 + qk2;
                unsigned b0 = *(const unsigned*)(bp);
                unsigned b1v = *(const unsigned*)(bp + 8);
                mma16816(acc[0][nt], a[0], b0, b1v);
                mma16816(acc[1][nt], a[1], b0, b1v);
            }
        }
    }

    #pragma unroll
    for (int mt = 0; mt < 2; mt++){
        #pragma unroll
        for (int half = 0; half < 2; half++){
            int r = mt*16 + qrow + half*8;
            if (s0 + r < n){
                int bb = bl[r];
                float* dst = g_base + ((size_t)e*B + bb)*512;
                #pragma unroll
                for (int nt = 0; nt < 4; nt++){
                    int h = nb + nt*8 + qk2;
                    float2 o;
                    o.x = acc[mt][nt][half*2    ] + b1[e*512 + h];
                    o.y = acc[mt][nt][half*2 + 1] + b1[e*512 + h + 1];
                    *(float2*)(dst + h) = o;
                }
            }
        }
    }
}

// ---------------- K4: expert MLP (R9 shape, tiled B loads) ----------------
__global__ void __launch_bounds__(128, 5)
k_expert(const float* __restrict__ fut, const float* __restrict__ eps,
         const int* __restrict__ t, const float* __restrict__ b2){
    extern __shared__ char smraw[];
    __nv_bfloat16* nzs = (__nv_bfloat16*)smraw;       // 32 x 72
    __nv_bfloat16* hss = nzs + 32*72;                 // 32 x 520
    float* basev = (float*)(hss + 32*520);            // 512
    __shared__ float red[4];

    int p2 = blockIdx.x;
    int p = p2 >> 1, mhalf = p2 & 1;
    int b, e;
    if (p < 24){ b = p / 6; e = p - b*6; }
    else       { b = p - 20; e = g_sel[p - 20]; }
    int tid = threadIdx.x;
    bool do_loss  = (e == g_sel[b]);
    bool do_store = (b < 4);

    float ab = g_ab[t[b]];
    float sa = sqrtf(ab), sb = sqrtf(1.0f - ab);

    {
        int r = tid >> 2, c0 = (tid & 3) * 16;
        int gr = mhalf*32 + r;
        const float4* f4 = (const float4*)(fut + (size_t)b*4096 + gr*64 + c0);
        const float4* e4 = (const float4*)(eps + (size_t)b*4096 + gr*64 + c0);
        __nv_bfloat16* dst = nzs + r*72 + c0;
        #pragma unroll
        for (int i = 0; i < 4; i++){
            float4 vf = f4[i], ve = e4[i];
            *(__nv_bfloat162*)(dst + i*4    ) = __floats2bfloat162_rn(fmaf(sa,vf.x,sb*ve.x), fmaf(sa,vf.y,sb*ve.y));
            *(__nv_bfloat162*)(dst + i*4 + 2) = __floats2bfloat162_rn(fmaf(sa,vf.z,sb*ve.z), fmaf(sa,vf.w,sb*ve.w));
        }
    }
    #pragma unroll
    for (int i = 0; i < 4; i++)
        basev[tid + i*128] = g_base[((size_t)e*B + b)*512 + tid + i*128];
    __syncthreads();

    int warp = tid >> 5, lane = tid & 31;
    int qrow = lane >> 2, qk2 = (lane & 3) * 2;

    // ---- phase1: warp owns 128 h-cols, M=32 local ----
    {
        int n0 = warp * 128;
        const __nv_bfloat16* W1nE = c_W1n + (size_t)e*32768;

        unsigned a[2][4][4];
        #pragma unroll
        for (int mt = 0; mt < 2; mt++)
            #pragma unroll
            for (int ks = 0; ks < 4; ks++){
                const __nv_bfloat16* ap = nzs + (mt*16 + qrow)*72 + ks*16 + qk2;
                a[mt][ks][0] = *(const unsigned*)(ap);
                a[mt][ks][1] = *(const unsigned*)(ap + 8*72);
                a[mt][ks][2] = *(const unsigned*)(ap + 8);
                a[mt][ks][3] = *(const unsigned*)(ap + 8*72 + 8);
            }

        #pragma unroll 4
        for (int nto = 0; nto < 16; nto++){
            int h8 = n0 + nto*8;
            int hg = warp*16 + nto;
            unsigned bfr[4][2];
            #pragma unroll
            for (int ks = 0; ks < 4; ks++){
                const __nv_bfloat16* bp = W1nE + (hg*4 + ks)*128 + qrow*16 + qk2;
                bfr[ks][0] = *(const unsigned*)(bp);
                bfr[ks][1] = *(const unsigned*)(bp + 8);
            }
            float c0v[2][4];
            #pragma unroll
            for (int mt = 0; mt < 2; mt++)
                #pragma unroll
                for (int r = 0; r < 4; r++) c0v[mt][r] = 0.0f;
            #pragma unroll
            for (int ks = 0; ks < 4; ks++){
                #pragma unroll
                for (int mt = 0; mt < 2; mt++)
                    mma16816(c0v[mt], a[mt][ks], bfr[ks][0], bfr[ks][1]);
            }
            int h = h8 + qk2;
            float ba0 = basev[h], ba1 = basev[h+1];
            #pragma unroll
            for (int mt = 0; mt < 2; mt++){
                int r = mt*16 + qrow;
                *(__nv_bfloat162*)(hss + r*520 + h) =
                    __floats2bfloat162_rn(gelu_fast(c0v[mt][0] + ba0), gelu_fast(c0v[mt][1] + ba1));
                *(__nv_bfloat162*)(hss + (r+8)*520 + h) =
                    __floats2bfloat162_rn(gelu_fast(c0v[mt][2] + ba0), gelu_fast(c0v[mt][3] + ba1));
            }
        }
    }
    __syncthreads();

    // ---- phase2: warp owns 16 f-cols, M=32 local, K=512 ----
    int f0 = warp * 16;
    const __nv_bfloat16* W2tE = c_W2t + (size_t)e*32768;

    float acc[2][2][4];
    #pragma unroll
    for (int mt = 0; mt < 2; mt++)
        #pragma unroll
        for (int nt = 0; nt < 2; nt++)
            #pragma unroll
            for (int r = 0; r < 4; r++) acc[mt][nt][r] = 0.0f;

    #pragma unroll 8
    for (int ks = 0; ks < 32; ks++){
        unsigned bfr[2][2];
        #pragma unroll
        for (int nt = 0; nt < 2; nt++){
            int fg = warp*2 + nt;
            const __nv_bfloat16* bp = W2tE + (fg*32 + ks)*128 + qrow*16 + qk2;
            bfr[nt][0] = *(const unsigned*)(bp);
            bfr[nt][1] = *(const unsigned*)(bp + 8);
        }
        #pragma unroll
        for (int mt = 0; mt < 2; mt++){
            const __nv_bfloat16* ap = hss + (mt*16 + qrow)*520 + ks*16 + qk2;
            unsigned a2[4];
            a2[0] = *(const unsigned*)(ap);
            a2[1] = *(const unsigned*)(ap + 8*520);
            a2[2] = *(const unsigned*)(ap + 8);
            a2[3] = *(const unsigned*)(ap + 8*520 + 8);
            mma16816(acc[mt][0], a2, bfr[0][0], bfr[0][1]);
            mma16816(acc[mt][1], a2, bfr[1][0], bfr[1][1]);
        }
    }

    float lsum = 0.0f;
    #pragma unroll
    for (int mt = 0; mt < 2; mt++){
        #pragma unroll
        for (int nt = 0; nt < 2; nt++){
            int fcol = f0 + nt*8 + qk2;
            float bb0 = b2[e*64 + fcol], bb1 = b2[e*64 + fcol + 1];
            #pragma unroll
            for (int h2 = 0; h2 < 2; h2++){
                int rg = mhalf*32 + mt*16 + qrow + h2*8;
                float o0 = acc[mt][nt][h2*2    ] + bb0;
                float o1 = acc[mt][nt][h2*2 + 1] + bb1;
                if (do_store){
                    float2 st; st.x = o0; st.y = o1;
                    *(float2*)&g_outsub[((e*4 + b)*64 + rg)*64 + fcol] = st;
                }
                if (do_loss){
                    float2 ev = *(const float2*)&eps[(size_t)b*4096 + rg*64 + fcol];
                    float d0 = o0 - ev.x, d1 = o1 - ev.y;
                    lsum += d0*d0 + d1*d1;
                }
            }
        }
    }

    if (do_loss){
        #pragma unroll
        for (int off = 16; off; off >>= 1) lsum += __shfl_xor_sync(0xffffffff, lsum, off);
        if (lane == 0) red[warp] = lsum;
        __syncthreads();
        if (tid == 0){
            float tot = red[0] + red[1] + red[2] + red[3];
            atomicAdd(&g_loss[b], tot * (1.0f/4096.0f));
        }
    }
}

// ---------------- K5: parallel final reduction + last-block scalar ----------------
#define FIN_BLKS 96
__global__ void k_final(float* __restrict__ out){
    int bid = blockIdx.x, tid = threadIdx.x;
    if (bid < 2){
        __shared__ float sh[13];
        if (tid < 13) sh[tid] = 0.0f;
        __syncthreads();
        const float PW[3] = {1.0f, 5.0f, 5.0f};
        int b = bid*256 + tid;
        int s = g_sel[b];
        atomicAdd(&sh[0], g_loss[b] * PW[s % 3]);
        atomicAdd(&sh[1 + s], 1.0f);
        #pragma unroll
        for (int e = 0; e < 6; e++) atomicAdd(&sh[7 + e], g_probs[b*NE + e]);
        __syncthreads();
        if (tid == 0) atomicAdd(&g_accL, sh[0]);
        if (tid < 6){
            atomicAdd(&g_cntF[tid],  sh[1 + tid]);
            atomicAdd(&g_psumE[tid], sh[7 + tid]);
        }
    } else {
        int nb = FIN_BLKS - 2;
        int idx0 = (bid - 2)*256 + tid;
        int stride = nb*256;
        const int pa[7] = {0,1,3,4,0,1,2};
        const int pb[7] = {1,2,4,5,3,4,5};
        float ch = 0.0f;
        for (int i = idx0; i < 16384; i += stride){
            #pragma unroll
            for (int q = 0; q < 7; q++){
                float d = g_outsub[pa[q]*16384 + i] - g_outsub[pb[q]*16384 + i];
                ch += d*d;
            }
        }
        float smv = 0.0f;
        for (int i = idx0; i < 96768; i += stride){
            int e  = i / 16128; int r  = i - e*16128;
            int s  = r / 4032;  int r2 = r - s*4032;
            int idx = (e*4 + s)*4096 + r2;
            float d = g_outsub[idx + 64] - g_outsub[idx];
            smv += d*d;
        }
        #pragma unroll
        for (int off = 16; off; off >>= 1){
            ch  += __shfl_xor_sync(0xffffffff, ch,  off);
            smv += __shfl_xor_sync(0xffffffff, smv, off);
        }
        if ((tid & 31) == 0){
            atomicAdd(&g_accC, ch);
            atomicAdd(&g_accS, smv);
        }
    }

    __syncthreads();
    __shared__ bool amLast;
    if (tid == 0){
        __threadfence();
        unsigned old = atomicAdd(&g_finDone, 1u);
        amLast = (old == FIN_BLKS - 1);
    }
    __syncthreads();
    if (amLast && tid == 0){
        __threadfence();
        float lb = 0.0f;
        #pragma unroll
        for (int e = 0; e < 6; e++)
            lb += (g_cntF[e] / 512.0f) * (g_psumE[e] / 512.0f);
        out[0] = g_accL / 512.0f
               + 0.01f * (g_accC / 16384.0f + 0.5f * g_accS / 16128.0f)
               + 0.06f * lb;
    }
}

// ---------------- launch ----------------
extern "C" void kernel_launch(void* const* d_in, const int* in_sizes, int n_in,
                              void* d_out, int out_size){
    const float* obs  = (const float*)d_in[0];
    const float* fut  = (const float*)d_in[1];
    const float* sc   = (const float*)d_in[2];
    const float* eps  = (const float*)d_in[3];
    const int*   phase= (const int*)  d_in[4];
    const int*   t    = (const int*)  d_in[5];
    const float* Wenc = (const float*)d_in[6];
    const float* benc = (const float*)d_in[7];
    const float* Wstat= (const float*)d_in[8];
    const float* Wr   = (const float*)d_in[9];
    const float* br   = (const float*)d_in[10];
    const float* W1   = (const float*)d_in[11];
    const float* b1   = (const float*)d_in[12];
    const float* W2   = (const float*)d_in[13];
    const float* b2   = (const float*)d_in[14];

    const int SMEM_CTX  = 256*APAD*2 + 2*512*4;            // 40,960 B
    const int SMEM_BASE = 32*1032*2 + 128;                 // 66,176 B
    const int SMEM_EXP  = (32*72 + 32*520)*2 + 512*4;      // 39,936 B

    static bool once = false;
    static cudaStream_t s2;
    static cudaEvent_t evFork, evJoin;
    if (!once){
        cudaFuncSetAttribute(k_ctx_fused, cudaFuncAttributeMaxDynamicSharedMemorySize, SMEM_CTX);
        cudaFuncSetAttribute(k_base,      cudaFuncAttributeMaxDynamicSharedMemorySize, SMEM_BASE);
        cudaFuncSetAttribute(k_expert,    cudaFuncAttributeMaxDynamicSharedMemorySize, SMEM_EXP);
        cudaStreamCreateWithFlags(&s2, cudaStreamNonBlocking);
        cudaEventCreateWithFlags(&evFork, cudaEventDisableTiming);
        cudaEventCreateWithFlags(&evJoin, cudaEventDisableTiming);
        once = true;
    }

    k_init2<<<5, 256>>>(Wenc);

    cudaEventRecord(evFork, 0);
    cudaStreamWaitEvent(s2, evFork, 0);
    k_prep<<<3968, 256, 0, s2>>>(t, W1, W2);
    cudaEventRecord(evJoin, s2);

    k_ctx_fused<<<B, 512, SMEM_CTX>>>(obs, sc, benc, Wstat, Wr, br, phase);

    cudaStreamWaitEvent(0, evJoin, 0);

    k_base  <<<dim3(NE, 16, 2), 256, SMEM_BASE>>>(b1);
    k_expert<<<2*NPAIR, 128, SMEM_EXP>>>(fut, eps, t, b2);
    k_final <<<FIN_BLKS, 256>>>((float*)d_out);
}

// round 13
// speedup vs baseline: 1.3229x; 1.0378x over previous
#include <cuda_runtime.h>
#include <cuda_bf16.h>
#include <math.h>

#define B   512
#define TP  256
#define DM  512
#define DS  32
#define NE  6
#define NPAIR 532

// ---------------- device scratch ----------------
__device__ float g_ab[1000];
__device__ float g_gctx[B*DM];
__device__ float g_temb[B*DM];
__device__ float g_probs[B*NE];
__device__ int   g_sel[B];
__device__ float g_loss[B];
__device__ float g_outsub[NE*4*64*64];
__device__ int   g_cnt[NE];
__device__ int   g_list[NE*512];
__device__ float g_base[NE*B*512];
// fragment-tiled bf16 weights: each n8 x k16 tile contiguous as [r(8)][kk(16)] = 128 elems
__device__ __nv_bfloat16 c_Wenc[DM*64];                 // [ng 64][kg 4][128]
__device__ __nv_bfloat16 c_W1n[NE*512*64];              // [e][hg 64][kg 4][128]
__device__ __nv_bfloat16 c_W1b[(size_t)NE*512*1024];    // [e][hg 64][kg 64][128]
__device__ __nv_bfloat16 c_W2t[NE*64*512];              // [e][fg 8][kg 32][128]
__device__ float g_accL, g_accC, g_accS;
__device__ float g_psumE[NE];
__device__ float g_cntF[NE];
__device__ unsigned g_finDone;

__device__ __forceinline__ float gelu_fast(float x){
    float s = x*x;
    float p = x * fmaf(s, 0.044715f, 1.0f);
    float argv = p * -2.3022083f;
    float e;
    asm("ex2.approx.f32 %0, %1;" : "=f"(e) : "f"(argv));
    float r;
    asm("rcp.approx.f32 %0, %1;" : "=f"(r) : "f"(e + 1.0f));
    return x * r;
}

__device__ __forceinline__ void mma16816(float* c, const unsigned* a, unsigned b0, unsigned b1){
    asm("mma.sync.aligned.m16n8k16.row.col.f32.bf16.bf16.f32 "
        "{%0,%1,%2,%3}, {%4,%5,%6,%7}, {%8,%9}, {%0,%1,%2,%3};"
        : "+f"(c[0]), "+f"(c[1]), "+f"(c[2]), "+f"(c[3])
        : "r"(a[0]), "r"(a[1]), "r"(a[2]), "r"(a[3]), "r"(b0), "r"(b1));
}

// ---------------- K0: init scalars + Wenc convert (tiled) ----------------
__global__ void k_init2(const float* __restrict__ Wenc){
    int tid = threadIdx.x;
    if (blockIdx.x == 0){
        if (tid < NE){ g_cnt[tid] = 0; g_psumE[tid] = 0.0f; g_cntF[tid] = 0.0f; }
        if (tid == 6){ g_accL = 0.0f; g_accC = 0.0f; g_accS = 0.0f; g_finDone = 0u; }
        g_loss[tid] = 0.0f;
        g_loss[tid + 256] = 0.0f;
        if (tid == 0){
            float ab = 1.0f;
            const float step = (0.02f - 0.0001f) / 999.0f;
            for (int i = 0; i < 1000; i++){
                float beta = 0.0001f + step * (float)i;
                ab *= (1.0f - beta);
                g_ab[i] = ab;
            }
        }
    } else {
        int gid = (blockIdx.x - 1)*256 + tid;   // 1024 threads
        int n = gid >> 1, kh = (gid & 1) * 32;
        int ng = n >> 3, r = n & 7;
        #pragma unroll
        for (int i = 0; i < 32; i++){
            int k = kh + i;
            int kg = k >> 4, kk = k & 15;
            c_Wenc[(ng*4 + kg)*128 + r*16 + kk] = __float2bfloat16_rn(Wenc[k*DM + n]);
        }
    }
}

// ---------------- K1: merged prep (W1, W2 converts + temb + g_base zero) ----------------
__global__ void k_prep(const int* __restrict__ t,
                       const float* __restrict__ W1, const float* __restrict__ W2){
    __shared__ float sm[32][33];
    int bid = blockIdx.x;
    int tid = threadIdx.x;

    if (bid < 3264){                       // W1 convert
        int e = bid / 544, rem = bid - e*544;
        int kt = rem >> 4, ht = rem & 15;
        int i = tid >> 3, j4 = (tid & 7) * 4;
        float4 v = *(const float4*)&W1[((size_t)e*1088 + kt*32 + i)*512 + ht*32 + j4];
        sm[i][j4] = v.x; sm[i][j4+1] = v.y; sm[i][j4+2] = v.z; sm[i][j4+3] = v.w;
        __syncthreads();
        int h = ht*32 + i;
        int k = kt*32 + j4;
        __nv_bfloat162 p0 = __floats2bfloat162_rn(sm[j4][i],   sm[j4+1][i]);
        __nv_bfloat162 p1 = __floats2bfloat162_rn(sm[j4+2][i], sm[j4+3][i]);
        int hg = h >> 3, r = h & 7;
        __nv_bfloat16* dst;
        if (kt < 2){
            int kg = k >> 4, kk = k & 15;
            dst = c_W1n + (size_t)e*32768 + (hg*4 + kg)*128 + r*16 + kk;
        } else {
            int kp = k - 64;
            int kg = kp >> 4, kk = kp & 15;
            dst = c_W1b + (size_t)e*524288 + (size_t)(hg*64 + kg)*128 + r*16 + kk;
        }
        *(__nv_bfloat162*)dst       = p0;
        *(__nv_bfloat162*)(dst + 2) = p1;
    } else if (bid < 3456){                // W2 convert
        int idx2 = bid - 3264;
        int e = idx2 >> 5, rem = idx2 & 31;
        int ht = rem >> 1, ft = rem & 1;
        int i = tid >> 3, j4 = (tid & 7) * 4;
        float4 v = *(const float4*)&W2[((size_t)e*512 + ht*32 + i)*64 + ft*32 + j4];
        sm[i][j4] = v.x; sm[i][j4+1] = v.y; sm[i][j4+2] = v.z; sm[i][j4+3] = v.w;
        __syncthreads();
        int f = ft*32 + i;
        int h = ht*32 + j4;
        __nv_bfloat162 p0 = __floats2bfloat162_rn(sm[j4][i],   sm[j4+1][i]);
        __nv_bfloat162 p1 = __floats2bfloat162_rn(sm[j4+2][i], sm[j4+3][i]);
        int fg = f >> 3, r = f & 7;
        int kg = h >> 4, kk = h & 15;
        __nv_bfloat16* dst = c_W2t + (size_t)e*32768 + (fg*32 + kg)*128 + r*16 + kk;
        *(__nv_bfloat162*)dst       = p0;
        *(__nv_bfloat162*)(dst + 2) = p1;
    } else if (bid < 3968){                // temb
        int b = bid - 3456;
        float tv = (float)t[b];
        for (int j = tid; j < DM; j += 256){
            int i = (j < 256) ? j : (j - 256);
            float freq = expf(-9.210340371976184f * (float)i / 256.0f);
            float a = tv * freq;
            g_temb[b*DM + j] = (j < 256) ? sinf(a) : cosf(a);
        }
    } else {                               // zero g_base (64 blocks, float4 stride)
        int zb = bid - 3968;
        float4* p = (float4*)g_base;
        const int total4 = NE*B*512/4;     // 393216
        for (int i = zb*256 + tid; i < total4; i += 64*256){
            float4 z; z.x = 0.0f; z.y = 0.0f; z.z = 0.0f; z.w = 0.0f;
            p[i] = z;
        }
    }
}

// ---------------- K2: fused ctx GEMM + router ----------------
#define APAD 72
__global__ void __launch_bounds__(512, 1)
k_ctx_fused(const float* __restrict__ obs, const float* __restrict__ sc,
            const float* __restrict__ benc, const float* __restrict__ Wstat,
            const float* __restrict__ Wr, const float* __restrict__ br,
            const int* __restrict__ phase){
    extern __shared__ char smraw[];
    __nv_bfloat16* As = (__nv_bfloat16*)smraw;
    float* pre  = (float*)(As + 256*APAD);
    float* gbuf = pre + 512;

    int b = blockIdx.x;
    int tid = threadIdx.x;

    {
        int row = tid >> 1;
        int c0  = (tid & 1) * 32;
        const float4* src = (const float4*)(obs + (size_t)b*TP*64 + row*64 + c0);
        __nv_bfloat16* arow = As + row*APAD + c0;
        #pragma unroll
        for (int i = 0; i < 8; i++){
            float4 v = src[i];
            *(__nv_bfloat162*)(arow + i*4    ) = __floats2bfloat162_rn(v.x, v.y);
            *(__nv_bfloat162*)(arow + i*4 + 2) = __floats2bfloat162_rn(v.z, v.w);
        }
    }
    {
        float acc = benc[tid];
        #pragma unroll
        for (int k = 0; k < 32; k++) acc = fmaf(sc[b*DS + k], Wstat[k*DM + tid], acc);
        pre[tid] = acc;
    }
    __syncthreads();

    int warp = tid >> 5, lane = tid & 31;
    int qrow = lane >> 2, qk2 = (lane & 3) * 2;
    int n0 = warp * 32;

    unsigned bfr[4][4][2];
    #pragma unroll
    for (int nt = 0; nt < 4; nt++)
        #pragma unroll
        for (int ks = 0; ks < 4; ks++){
            const __nv_bfloat16* bp = c_Wenc + ((warp*4 + nt)*4 + ks)*128 + qrow*16 + qk2;
            bfr[nt][ks][0] = *(const unsigned*)(bp);
            bfr[nt][ks][1] = *(const unsigned*)(bp + 8);
        }
    float prev[4][2];
    #pragma unroll
    for (int nt = 0; nt < 4; nt++){
        prev[nt][0] = pre[n0 + nt*8 + qk2];
        prev[nt][1] = pre[n0 + nt*8 + qk2 + 1];
    }

    float s[4][2];
    #pragma unroll
    for (int nt = 0; nt < 4; nt++){ s[nt][0] = 0.0f; s[nt][1] = 0.0f; }

    #pragma unroll 2
    for (int mc = 0; mc < 8; mc++){
        unsigned a[2][4][4];
        #pragma unroll
        for (int mt = 0; mt < 2; mt++)
            #pragma unroll
            for (int ks = 0; ks < 4; ks++){
                const __nv_bfloat16* ap = As + (mc*32 + mt*16 + qrow)*APAD + ks*16 + qk2;
                a[mt][ks][0] = *(const unsigned*)(ap);
                a[mt][ks][1] = *(const unsigned*)(ap + 8*APAD);
                a[mt][ks][2] = *(const unsigned*)(ap + 8);
                a[mt][ks][3] = *(const unsigned*)(ap + 8*APAD + 8);
            }
        float c[2][4][4];
        #pragma unroll
        for (int mt = 0; mt < 2; mt++)
            #pragma unroll
            for (int nt = 0; nt < 4; nt++)
                #pragma unroll
                for (int r = 0; r < 4; r++) c[mt][nt][r] = 0.0f;
        #pragma unroll
        for (int ks = 0; ks < 4; ks++)
            #pragma unroll
            for (int mt = 0; mt < 2; mt++)
                #pragma unroll
                for (int nt = 0; nt < 4; nt++)
                    mma16816(c[mt][nt], a[mt][ks], bfr[nt][ks][0], bfr[nt][ks][1]);
        #pragma unroll
        for (int mt = 0; mt < 2; mt++)
            #pragma unroll
            for (int nt = 0; nt < 4; nt++){
                s[nt][0] += gelu_fast(c[mt][nt][0] + prev[nt][0]) + gelu_fast(c[mt][nt][2] + prev[nt][0]);
                s[nt][1] += gelu_fast(c[mt][nt][1] + prev[nt][1]) + gelu_fast(c[mt][nt][3] + prev[nt][1]);
            }
    }

    #pragma unroll
    for (int off = 16; off >= 4; off >>= 1)
        #pragma unroll
        for (int nt = 0; nt < 4; nt++){
            s[nt][0] += __shfl_xor_sync(0xffffffff, s[nt][0], off);
            s[nt][1] += __shfl_xor_sync(0xffffffff, s[nt][1], off);
        }
    if (qrow == 0){
        #pragma unroll
        for (int nt = 0; nt < 4; nt++){
            int j = n0 + nt*8 + qk2;
            float v0 = s[nt][0] * (1.0f/256.0f);
            float v1 = s[nt][1] * (1.0f/256.0f);
            gbuf[j] = v0; gbuf[j+1] = v1;
            g_gctx[b*DM + j]     = v0;
            g_gctx[b*DM + j + 1] = v1;
        }
    }
    __syncthreads();

    if (warp == 0){
        float p[6] = {0,0,0,0,0,0};
        for (int k = lane; k < DM; k += 32){
            float g = gbuf[k];
            const float* w = Wr + k*NE;
            #pragma unroll
            for (int e = 0; e < 6; e++) p[e] = fmaf(g, w[e], p[e]);
        }
        #pragma unroll
        for (int off = 16; off; off >>= 1)
            #pragma unroll
            for (int e = 0; e < 6; e++) p[e] += __shfl_xor_sync(0xffffffff, p[e], off);
        if (lane == 0){
            float l[6], pr[6];
            #pragma unroll
            for (int e = 0; e < 6; e++) l[e] = p[e] + br[e];
            float m = l[0];
            #pragma unroll
            for (int e = 1; e < 6; e++) m = fmaxf(m, l[e]);
            float sv = 0.0f;
            #pragma unroll
            for (int e = 0; e < 6; e++){ pr[e] = expf(l[e] - m); sv += pr[e]; }
            float inv = 1.0f / sv;
            #pragma unroll
            for (int e = 0; e < 6; e++){ pr[e] *= inv; g_probs[b*NE + e] = pr[e]; }
            int pl = phase[b];
            int sel = pl + ((pr[pl+3] > pr[pl]) ? 3 : 0);
            g_sel[b] = sel;
            if (b < 4){
                #pragma unroll
                for (int e = 0; e < 6; e++){
                    int idx = atomicAdd(&g_cnt[e], 1);
                    g_list[e*512 + idx] = b;
                }
            } else {
                int idx = atomicAdd(&g_cnt[sel], 1);
                g_list[sel*512 + idx] = b;
            }
        }
    }
}

// ---------------- K3c: base via bf16 MMA, k-split x4, atomic accumulate ----------------
#define BAPAD 264
__global__ void __launch_bounds__(256, 2)
k_base(const float* __restrict__ b1_unused){
    extern __shared__ char smraw[];
    __nv_bfloat16* As = (__nv_bfloat16*)smraw;   // 32 x 264 (256 k-cols + pad)
    int* bl = (int*)(As + 32*BAPAD);             // 32

    int e = blockIdx.x, tile = blockIdx.y;
    int hs = blockIdx.z & 1;       // h-half: 0 or 1 (256 cols each)
    int kq = blockIdx.z >> 1;      // k-chunk: 0..3 (256 k each)
    int n = g_cnt[e], s0 = tile*32;
    if (s0 >= n) return;
    int tid = threadIdx.x;

    if (tid < 32){
        int s = s0 + tid;
        bl[tid] = (s < n) ? g_list[e*512 + s] : g_list[e*512];
    }
    __syncthreads();

    {   // load 32 rows x 256 cols of (gctx|temb) k-chunk
        int r = tid >> 3, seg = tid & 7;   // seg: 32-col group
        int bb = bl[r];
        const float* srcbase = (kq < 2)
            ? (g_gctx + bb*512 + kq*256)
            : (g_temb + bb*512 + (kq - 2)*256);
        const float4* src = (const float4*)(srcbase + seg*32);
        __nv_bfloat16* dst = As + r*BAPAD + seg*32;
        #pragma unroll
        for (int i = 0; i < 8; i++){
            float4 v = src[i];
            *(__nv_bfloat162*)(dst + i*4    ) = __floats2bfloat162_rn(v.x, v.y);
            *(__nv_bfloat162*)(dst + i*4 + 2) = __floats2bfloat162_rn(v.z, v.w);
        }
    }
    __syncthreads();

    int warp = tid >> 5, lane = tid & 31;
    int qrow = lane >> 2;
    int qk2 = (lane & 3) * 2;
    int nb = hs*256 + warp*32;
    int hg0 = nb >> 3;
    const __nv_bfloat16* W1bE = c_W1b + (size_t)e*524288;

    float acc[2][4][4];
    #pragma unroll
    for (int mt = 0; mt < 2; mt++)
        #pragma unroll
        for (int nt = 0; nt < 4; nt++)
            #pragma unroll
            for (int r = 0; r < 4; r++) acc[mt][nt][r] = 0.0f;

    #pragma unroll
    for (int kc = 0; kc < 4; kc++){
        #pragma unroll
        for (int ks = 0; ks < 4; ks++){
            int kof = kc*64 + ks*16 + qk2;          // local k offset in As
            int kg = kq*16 + kc*4 + ks;             // global k16-group
            unsigned a[2][4];
            #pragma unroll
            for (int mt = 0; mt < 2; mt++){
                const __nv_bfloat16* ap = As + (mt*16 + qrow)*BAPAD + kof;
                a[mt][0] = *(const unsigned*)(ap);
                a[mt][1] = *(const unsigned*)(ap + 8*BAPAD);
                a[mt][2] = *(const unsigned*)(ap + 8);
                a[mt][3] = *(const unsigned*)(ap + 8*BAPAD + 8);
            }
            #pragma unroll
            for (int nt = 0; nt < 4; nt++){
                const __nv_bfloat16* bp = W1bE + (size_t)((hg0 + nt)*64 + kg)*128 + qrow*16 + qk2;
                unsigned b0 = *(const unsigned*)(bp);
                unsigned b1v = *(const unsigned*)(bp + 8);
                mma16816(acc[0][nt], a[0], b0, b1v);
                mma16816(acc[1][nt], a[1], b0, b1v);
            }
        }
    }

    #pragma unroll
    for (int mt = 0; mt < 2; mt++){
        #pragma unroll
        for (int half = 0; half < 2; half++){
            int r = mt*16 + qrow + half*8;
            if (s0 + r < n){
                int bb = bl[r];
                float* dst = g_base + ((size_t)e*B + bb)*512;
                #pragma unroll
                for (int nt = 0; nt < 4; nt++){
                    int h = nb + nt*8 + qk2;
                    atomicAdd(&dst[h],     acc[mt][nt][half*2    ]);
                    atomicAdd(&dst[h + 1], acc[mt][nt][half*2 + 1]);
                }
            }
        }
    }
}

// ---------------- K4: expert MLP (R12, b1 added at basev load) ----------------
__global__ void __launch_bounds__(128, 5)
k_expert(const float* __restrict__ fut, const float* __restrict__ eps,
         const int* __restrict__ t, const float* __restrict__ b2,
         const float* __restrict__ b1){
    extern __shared__ char smraw[];
    __nv_bfloat16* nzs = (__nv_bfloat16*)smraw;       // 32 x 72
    __nv_bfloat16* hss = nzs + 32*72;                 // 32 x 520
    float* basev = (float*)(hss + 32*520);            // 512
    __shared__ float red[4];

    int p2 = blockIdx.x;
    int p = p2 >> 1, mhalf = p2 & 1;
    int b, e;
    if (p < 24){ b = p / 6; e = p - b*6; }
    else       { b = p - 20; e = g_sel[p - 20]; }
    int tid = threadIdx.x;
    bool do_loss  = (e == g_sel[b]);
    bool do_store = (b < 4);

    float ab = g_ab[t[b]];
    float sa = sqrtf(ab), sb = sqrtf(1.0f - ab);

    {
        int r = tid >> 2, c0 = (tid & 3) * 16;
        int gr = mhalf*32 + r;
        const float4* f4 = (const float4*)(fut + (size_t)b*4096 + gr*64 + c0);
        const float4* e4 = (const float4*)(eps + (size_t)b*4096 + gr*64 + c0);
        __nv_bfloat16* dst = nzs + r*72 + c0;
        #pragma unroll
        for (int i = 0; i < 4; i++){
            float4 vf = f4[i], ve = e4[i];
            *(__nv_bfloat162*)(dst + i*4    ) = __floats2bfloat162_rn(fmaf(sa,vf.x,sb*ve.x), fmaf(sa,vf.y,sb*ve.y));
            *(__nv_bfloat162*)(dst + i*4 + 2) = __floats2bfloat162_rn(fmaf(sa,vf.z,sb*ve.z), fmaf(sa,vf.w,sb*ve.w));
        }
    }
    #pragma unroll
    for (int i = 0; i < 4; i++){
        int idx = tid + i*128;
        basev[idx] = g_base[((size_t)e*B + b)*512 + idx] + b1[e*512 + idx];
    }
    __syncthreads();

    int warp = tid >> 5, lane = tid & 31;
    int qrow = lane >> 2, qk2 = (lane & 3) * 2;

    // ---- phase1: warp owns 128 h-cols, M=32 local ----
    {
        int n0 = warp * 128;
        const __nv_bfloat16* W1nE = c_W1n + (size_t)e*32768;

        unsigned a[2][4][4];
        #pragma unroll
        for (int mt = 0; mt < 2; mt++)
            #pragma unroll
            for (int ks = 0; ks < 4; ks++){
                const __nv_bfloat16* ap = nzs + (mt*16 + qrow)*72 + ks*16 + qk2;
                a[mt][ks][0] = *(const unsigned*)(ap);
                a[mt][ks][1] = *(const unsigned*)(ap + 8*72);
                a[mt][ks][2] = *(const unsigned*)(ap + 8);
                a[mt][ks][3] = *(const unsigned*)(ap + 8*72 + 8);
            }

        #pragma unroll 4
        for (int nto = 0; nto < 16; nto++){
            int h8 = n0 + nto*8;
            int hg = warp*16 + nto;
            unsigned bfr[4][2];
            #pragma unroll
            for (int ks = 0; ks < 4; ks++){
                const __nv_bfloat16* bp = W1nE + (hg*4 + ks)*128 + qrow*16 + qk2;
                bfr[ks][0] = *(const unsigned*)(bp);
                bfr[ks][1] = *(const unsigned*)(bp + 8);
            }
            float c0v[2][4];
            #pragma unroll
            for (int mt = 0; mt < 2; mt++)
                #pragma unroll
                for (int r = 0; r < 4; r++) c0v[mt][r] = 0.0f;
            #pragma unroll
            for (int ks = 0; ks < 4; ks++){
                #pragma unroll
                for (int mt = 0; mt < 2; mt++)
                    mma16816(c0v[mt], a[mt][ks], bfr[ks][0], bfr[ks][1]);
            }
            int h = h8 + qk2;
            float ba0 = basev[h], ba1 = basev[h+1];
            #pragma unroll
            for (int mt = 0; mt < 2; mt++){
                int r = mt*16 + qrow;
                *(__nv_bfloat162*)(hss + r*520 + h) =
                    __floats2bfloat162_rn(gelu_fast(c0v[mt][0] + ba0), gelu_fast(c0v[mt][1] + ba1));
                *(__nv_bfloat162*)(hss + (r+8)*520 + h) =
                    __floats2bfloat162_rn(gelu_fast(c0v[mt][2] + ba0), gelu_fast(c0v[mt][3] + ba1));
            }
        }
    }
    __syncthreads();

    // ---- phase2: warp owns 16 f-cols, M=32 local, K=512 ----
    int f0 = warp * 16;
    const __nv_bfloat16* W2tE = c_W2t + (size_t)e*32768;

    float acc[2][2][4];
    #pragma unroll
    for (int mt = 0; mt < 2; mt++)
        #pragma unroll
        for (int nt = 0; nt < 2; nt++)
            #pragma unroll
            for (int r = 0; r < 4; r++) acc[mt][nt][r] = 0.0f;

    #pragma unroll 8
    for (int ks = 0; ks < 32; ks++){
        unsigned bfr[2][2];
        #pragma unroll
        for (int nt = 0; nt < 2; nt++){
            int fg = warp*2 + nt;
            const __nv_bfloat16* bp = W2tE + (fg*32 + ks)*128 + qrow*16 + qk2;
            bfr[nt][0] = *(const unsigned*)(bp);
            bfr[nt][1] = *(const unsigned*)(bp + 8);
        }
        #pragma unroll
        for (int mt = 0; mt < 2; mt++){
            const __nv_bfloat16* ap = hss + (mt*16 + qrow)*520 + ks*16 + qk2;
            unsigned a2[4];
            a2[0] = *(const unsigned*)(ap);
            a2[1] = *(const unsigned*)(ap + 8*520);
            a2[2] = *(const unsigned*)(ap + 8);
            a2[3] = *(const unsigned*)(ap + 8*520 + 8);
            mma16816(acc[mt][0], a2, bfr[0][0], bfr[0][1]);
            mma16816(acc[mt][1], a2, bfr[1][0], bfr[1][1]);
        }
    }

    float lsum = 0.0f;
    #pragma unroll
    for (int mt = 0; mt < 2; mt++){
        #pragma unroll
        for (int nt = 0; nt < 2; nt++){
            int fcol = f0 + nt*8 + qk2;
            float bb0 = b2[e*64 + fcol], bb1 = b2[e*64 + fcol + 1];
            #pragma unroll
            for (int h2 = 0; h2 < 2; h2++){
                int rg = mhalf*32 + mt*16 + qrow + h2*8;
                float o0 = acc[mt][nt][h2*2    ] + bb0;
                float o1 = acc[mt][nt][h2*2 + 1] + bb1;
                if (do_store){
                    float2 st; st.x = o0; st.y = o1;
                    *(float2*)&g_outsub[((e*4 + b)*64 + rg)*64 + fcol] = st;
                }
                if (do_loss){
                    float2 ev = *(const float2*)&eps[(size_t)b*4096 + rg*64 + fcol];
                    float d0 = o0 - ev.x, d1 = o1 - ev.y;
                    lsum += d0*d0 + d1*d1;
                }
            }
        }
    }

    if (do_loss){
        #pragma unroll
        for (int off = 16; off; off >>= 1) lsum += __shfl_xor_sync(0xffffffff, lsum, off);
        if (lane == 0) red[warp] = lsum;
        __syncthreads();
        if (tid == 0){
            float tot = red[0] + red[1] + red[2] + red[3];
            atomicAdd(&g_loss[b], tot * (1.0f/4096.0f));
        }
    }
}

// ---------------- K5: parallel final reduction + last-block scalar ----------------
#define FIN_BLKS 96
__global__ void k_final(float* __restrict__ out){
    int bid = blockIdx.x, tid = threadIdx.x;
    if (bid < 2){
        __shared__ float sh[13];
        if (tid < 13) sh[tid] = 0.0f;
        __syncthreads();
        const float PW[3] = {1.0f, 5.0f, 5.0f};
        int b = bid*256 + tid;
        int s = g_sel[b];
        atomicAdd(&sh[0], g_loss[b] * PW[s % 3]);
        atomicAdd(&sh[1 + s], 1.0f);
        #pragma unroll
        for (int e = 0; e < 6; e++) atomicAdd(&sh[7 + e], g_probs[b*NE + e]);
        __syncthreads();
        if (tid == 0) atomicAdd(&g_accL, sh[0]);
        if (tid < 6){
            atomicAdd(&g_cntF[tid],  sh[1 + tid]);
            atomicAdd(&g_psumE[tid], sh[7 + tid]);
        }
    } else {
        int nb = FIN_BLKS - 2;
        int idx0 = (bid - 2)*256 + tid;
        int stride = nb*256;
        const int pa[7] = {0,1,3,4,0,1,2};
        const int pb[7] = {1,2,4,5,3,4,5};
        float ch = 0.0f;
        for (int i = idx0; i < 16384; i += stride){
            #pragma unroll
            for (int q = 0; q < 7; q++){
                float d = g_outsub[pa[q]*16384 + i] - g_outsub[pb[q]*16384 + i];
                ch += d*d;
            }
        }
        float smv = 0.0f;
        for (int i = idx0; i < 96768; i += stride){
            int e  = i / 16128; int r  = i - e*16128;
            int s  = r / 4032;  int r2 = r - s*4032;
            int idx = (e*4 + s)*4096 + r2;
            float d = g_outsub[idx + 64] - g_outsub[idx];
            smv += d*d;
        }
        #pragma unroll
        for (int off = 16; off; off >>= 1){
            ch  += __shfl_xor_sync(0xffffffff, ch,  off);
            smv += __shfl_xor_sync(0xffffffff, smv, off);
        }
        if ((tid & 31) == 0){
            atomicAdd(&g_accC, ch);
            atomicAdd(&g_accS, smv);
        }
    }

    __syncthreads();
    __shared__ bool amLast;
    if (tid == 0){
        __threadfence();
        unsigned old = atomicAdd(&g_finDone, 1u);
        amLast = (old == FIN_BLKS - 1);
    }
    __syncthreads();
    if (amLast && tid == 0){
        __threadfence();
        float lb = 0.0f;
        #pragma unroll
        for (int e = 0; e < 6; e++)
            lb += (g_cntF[e] / 512.0f) * (g_psumE[e] / 512.0f);
        out[0] = g_accL / 512.0f
               + 0.01f * (g_accC / 16384.0f + 0.5f * g_accS / 16128.0f)
               + 0.06f * lb;
    }
}

// ---------------- launch ----------------
extern "C" void kernel_launch(void* const* d_in, const int* in_sizes, int n_in,
                              void* d_out, int out_size){
    const float* obs  = (const float*)d_in[0];
    const float* fut  = (const float*)d_in[1];
    const float* sc   = (const float*)d_in[2];
    const float* eps  = (const float*)d_in[3];
    const int*   phase= (const int*)  d_in[4];
    const int*   t    = (const int*)  d_in[5];
    const float* Wenc = (const float*)d_in[6];
    const float* benc = (const float*)d_in[7];
    const float* Wstat= (const float*)d_in[8];
    const float* Wr   = (const float*)d_in[9];
    const float* br   = (const float*)d_in[10];
    const float* W1   = (const float*)d_in[11];
    const float* b1   = (const float*)d_in[12];
    const float* W2   = (const float*)d_in[13];
    const float* b2   = (const float*)d_in[14];

    const int SMEM_CTX  = 256*APAD*2 + 2*512*4;            // 40,960 B
    const int SMEM_BASE = 32*BAPAD*2 + 128;                // 17,024 B
    const int SMEM_EXP  = (32*72 + 32*520)*2 + 512*4;      // 39,936 B

    static bool once = false;
    static cudaStream_t s2;
    static cudaEvent_t evFork, evJoin;
    if (!once){
        cudaFuncSetAttribute(k_ctx_fused, cudaFuncAttributeMaxDynamicSharedMemorySize, SMEM_CTX);
        cudaFuncSetAttribute(k_base,      cudaFuncAttributeMaxDynamicSharedMemorySize, SMEM_BASE);
        cudaFuncSetAttribute(k_expert,    cudaFuncAttributeMaxDynamicSharedMemorySize, SMEM_EXP);
        cudaStreamCreateWithFlags(&s2, cudaStreamNonBlocking);
        cudaEventCreateWithFlags(&evFork, cudaEventDisableTiming);
        cudaEventCreateWithFlags(&evJoin, cudaEventDisableTiming);
        once = true;
    }

    k_init2<<<5, 256>>>(Wenc);

    cudaEventRecord(evFork, 0);
    cudaStreamWaitEvent(s2, evFork, 0);
    k_prep<<<4032, 256, 0, s2>>>(t, W1, W2);
    cudaEventRecord(evJoin, s2);

    k_ctx_fused<<<B, 512, SMEM_CTX>>>(obs, sc, benc, Wstat, Wr, br, phase);

    cudaStreamWaitEvent(0, evJoin, 0);

    k_base  <<<dim3(NE, 16, 8), 256, SMEM_BASE>>>(b1);
    k_expert<<<2*NPAIR, 128, SMEM_EXP>>>(fut, eps, t, b2, b1);
    k_final <<<FIN_BLKS, 256>>>((float*)d_out);
}

// round 14
// speedup vs baseline: 1.5120x; 1.1429x over previous
#include <cuda_runtime.h>
#include <cuda_bf16.h>
#include <math.h>

#define B   512
#define TP  256
#define DM  512
#define DS  32
#define NE  6
#define NPAIR 532

// ---------------- device scratch ----------------
__device__ float g_ab[1000];
__device__ float g_gctx[B*DM];
__device__ float g_temb[B*DM];
__device__ float g_probs[B*NE];
__device__ int   g_sel[B];
__device__ float g_loss[B];
__device__ float g_outsub[NE*4*64*64];
__device__ int   g_cnt[NE];
__device__ int   g_list[NE*512];
__device__ float g_base[NE*B*512];
// fragment-tiled bf16 weights: each n8 x k16 tile contiguous as [r(8)][kk(16)] = 128 elems
__device__ __nv_bfloat16 c_Wenc[DM*64];                 // [ng 64][kg 4][128]
__device__ __nv_bfloat16 c_W1n[NE*512*64];              // [e][hg 64][kg 4][128]
__device__ __nv_bfloat16 c_W1b[(size_t)NE*512*1024];    // [e][hg 64][kg 64][128]
__device__ __nv_bfloat16 c_W2t[NE*64*512];              // [e][fg 8][kg 32][128]
__device__ float g_accL, g_accC, g_accS;
__device__ float g_psumE[NE];
__device__ float g_cntF[NE];
__device__ unsigned g_finDone;

// gelu tanh-form with single-MUFU hardware tanh
__device__ __forceinline__ float gelu_fast(float x){
    float s = x*x;
    float u = 0.7978845608028654f * x * fmaf(s, 0.044715f, 1.0f);
    float th;
    asm("tanh.approx.f32 %0, %1;" : "=f"(th) : "f"(u));
    return 0.5f * x * (1.0f + th);
}

__device__ __forceinline__ void mma16816(float* c, const unsigned* a, unsigned b0, unsigned b1){
    asm("mma.sync.aligned.m16n8k16.row.col.f32.bf16.bf16.f32 "
        "{%0,%1,%2,%3}, {%4,%5,%6,%7}, {%8,%9}, {%0,%1,%2,%3};"
        : "+f"(c[0]), "+f"(c[1]), "+f"(c[2]), "+f"(c[3])
        : "r"(a[0]), "r"(a[1]), "r"(a[2]), "r"(a[3]), "r"(b0), "r"(b1));
}

// ---------------- K0: init scalars + Wenc convert (tiled) ----------------
__global__ void k_init2(const float* __restrict__ Wenc){
    int tid = threadIdx.x;
    if (blockIdx.x == 0){
        if (tid < NE){ g_cnt[tid] = 0; g_psumE[tid] = 0.0f; g_cntF[tid] = 0.0f; }
        if (tid == 6){ g_accL = 0.0f; g_accC = 0.0f; g_accS = 0.0f; g_finDone = 0u; }
        g_loss[tid] = 0.0f;
        g_loss[tid + 256] = 0.0f;
        if (tid == 0){
            float ab = 1.0f;
            const float step = (0.02f - 0.0001f) / 999.0f;
            for (int i = 0; i < 1000; i++){
                float beta = 0.0001f + step * (float)i;
                ab *= (1.0f - beta);
                g_ab[i] = ab;
            }
        }
    } else {
        int gid = (blockIdx.x - 1)*256 + tid;   // 1024 threads
        int n = gid >> 1, kh = (gid & 1) * 32;
        int ng = n >> 3, r = n & 7;
        #pragma unroll
        for (int i = 0; i < 32; i++){
            int k = kh + i;
            int kg = k >> 4, kk = k & 15;
            c_Wenc[(ng*4 + kg)*128 + r*16 + kk] = __float2bfloat16_rn(Wenc[k*DM + n]);
        }
    }
}

// ---------------- K1: merged prep (W1, W2 converts + temb + g_base zero) ----------------
__global__ void k_prep(const int* __restrict__ t,
                       const float* __restrict__ W1, const float* __restrict__ W2){
    __shared__ float sm[32][33];
    int bid = blockIdx.x;
    int tid = threadIdx.x;

    if (bid < 3264){                       // W1 convert
        int e = bid / 544, rem = bid - e*544;
        int kt = rem >> 4, ht = rem & 15;
        int i = tid >> 3, j4 = (tid & 7) * 4;
        float4 v = *(const float4*)&W1[((size_t)e*1088 + kt*32 + i)*512 + ht*32 + j4];
        sm[i][j4] = v.x; sm[i][j4+1] = v.y; sm[i][j4+2] = v.z; sm[i][j4+3] = v.w;
        __syncthreads();
        int h = ht*32 + i;
        int k = kt*32 + j4;
        __nv_bfloat162 p0 = __floats2bfloat162_rn(sm[j4][i],   sm[j4+1][i]);
        __nv_bfloat162 p1 = __floats2bfloat162_rn(sm[j4+2][i], sm[j4+3][i]);
        int hg = h >> 3, r = h & 7;
        __nv_bfloat16* dst;
        if (kt < 2){
            int kg = k >> 4, kk = k & 15;
            dst = c_W1n + (size_t)e*32768 + (hg*4 + kg)*128 + r*16 + kk;
        } else {
            int kp = k - 64;
            int kg = kp >> 4, kk = kp & 15;
            dst = c_W1b + (size_t)e*524288 + (size_t)(hg*64 + kg)*128 + r*16 + kk;
        }
        *(__nv_bfloat162*)dst       = p0;
        *(__nv_bfloat162*)(dst + 2) = p1;
    } else if (bid < 3456){                // W2 convert
        int idx2 = bid - 3264;
        int e = idx2 >> 5, rem = idx2 & 31;
        int ht = rem >> 1, ft = rem & 1;
        int i = tid >> 3, j4 = (tid & 7) * 4;
        float4 v = *(const float4*)&W2[((size_t)e*512 + ht*32 + i)*64 + ft*32 + j4];
        sm[i][j4] = v.x; sm[i][j4+1] = v.y; sm[i][j4+2] = v.z; sm[i][j4+3] = v.w;
        __syncthreads();
        int f = ft*32 + i;
        int h = ht*32 + j4;
        __nv_bfloat162 p0 = __floats2bfloat162_rn(sm[j4][i],   sm[j4+1][i]);
        __nv_bfloat162 p1 = __floats2bfloat162_rn(sm[j4+2][i], sm[j4+3][i]);
        int fg = f >> 3, r = f & 7;
        int kg = h >> 4, kk = h & 15;
        __nv_bfloat16* dst = c_W2t + (size_t)e*32768 + (fg*32 + kg)*128 + r*16 + kk;
        *(__nv_bfloat162*)dst       = p0;
        *(__nv_bfloat162*)(dst + 2) = p1;
    } else if (bid < 3968){                // temb
        int b = bid - 3456;
        float tv = (float)t[b];
        for (int j = tid; j < DM; j += 256){
            int i = (j < 256) ? j : (j - 256);
            float freq = expf(-9.210340371976184f * (float)i / 256.0f);
            float a = tv * freq;
            g_temb[b*DM + j] = (j < 256) ? sinf(a) : cosf(a);
        }
    } else {                               // zero g_base (64 blocks, float4 stride)
        int zb = bid - 3968;
        float4* p = (float4*)g_base;
        const int total4 = NE*B*512/4;     // 393216
        for (int i = zb*256 + tid; i < total4; i += 64*256){
            float4 z; z.x = 0.0f; z.y = 0.0f; z.z = 0.0f; z.w = 0.0f;
            p[i] = z;
        }
    }
}

// ---------------- K2: fused ctx GEMM + router ----------------
#define APAD 72
__global__ void __launch_bounds__(512, 1)
k_ctx_fused(const float* __restrict__ obs, const float* __restrict__ sc,
            const float* __restrict__ benc, const float* __restrict__ Wstat,
            const float* __restrict__ Wr, const float* __restrict__ br,
            const int* __restrict__ phase){
    extern __shared__ char smraw[];
    __nv_bfloat16* As = (__nv_bfloat16*)smraw;
    float* pre  = (float*)(As + 256*APAD);
    float* gbuf = pre + 512;

    int b = blockIdx.x;
    int tid = threadIdx.x;

    {
        int row = tid >> 1;
        int c0  = (tid & 1) * 32;
        const float4* src = (const float4*)(obs + (size_t)b*TP*64 + row*64 + c0);
        __nv_bfloat16* arow = As + row*APAD + c0;
        #pragma unroll
        for (int i = 0; i < 8; i++){
            float4 v = src[i];
            *(__nv_bfloat162*)(arow + i*4    ) = __floats2bfloat162_rn(v.x, v.y);
            *(__nv_bfloat162*)(arow + i*4 + 2) = __floats2bfloat162_rn(v.z, v.w);
        }
    }
    {
        float acc = benc[tid];
        #pragma unroll
        for (int k = 0; k < 32; k++) acc = fmaf(sc[b*DS + k], Wstat[k*DM + tid], acc);
        pre[tid] = acc;
    }
    __syncthreads();

    int warp = tid >> 5, lane = tid & 31;
    int qrow = lane >> 2, qk2 = (lane & 3) * 2;
    int n0 = warp * 32;

    unsigned bfr[4][4][2];
    #pragma unroll
    for (int nt = 0; nt < 4; nt++)
        #pragma unroll
        for (int ks = 0; ks < 4; ks++){
            const __nv_bfloat16* bp = c_Wenc + ((warp*4 + nt)*4 + ks)*128 + qrow*16 + qk2;
            bfr[nt][ks][0] = *(const unsigned*)(bp);
            bfr[nt][ks][1] = *(const unsigned*)(bp + 8);
        }
    float prev[4][2];
    #pragma unroll
    for (int nt = 0; nt < 4; nt++){
        prev[nt][0] = pre[n0 + nt*8 + qk2];
        prev[nt][1] = pre[n0 + nt*8 + qk2 + 1];
    }

    float s[4][2];
    #pragma unroll
    for (int nt = 0; nt < 4; nt++){ s[nt][0] = 0.0f; s[nt][1] = 0.0f; }

    #pragma unroll 2
    for (int mc = 0; mc < 8; mc++){
        unsigned a[2][4][4];
        #pragma unroll
        for (int mt = 0; mt < 2; mt++)
            #pragma unroll
            for (int ks = 0; ks < 4; ks++){
                const __nv_bfloat16* ap = As + (mc*32 + mt*16 + qrow)*APAD + ks*16 + qk2;
                a[mt][ks][0] = *(const unsigned*)(ap);
                a[mt][ks][1] = *(const unsigned*)(ap + 8*APAD);
                a[mt][ks][2] = *(const unsigned*)(ap + 8);
                a[mt][ks][3] = *(const unsigned*)(ap + 8*APAD + 8);
            }
        float c[2][4][4];
        #pragma unroll
        for (int mt = 0; mt < 2; mt++)
            #pragma unroll
            for (int nt = 0; nt < 4; nt++)
                #pragma unroll
                for (int r = 0; r < 4; r++) c[mt][nt][r] = 0.0f;
        #pragma unroll
        for (int ks = 0; ks < 4; ks++)
            #pragma unroll
            for (int mt = 0; mt < 2; mt++)
                #pragma unroll
                for (int nt = 0; nt < 4; nt++)
                    mma16816(c[mt][nt], a[mt][ks], bfr[nt][ks][0], bfr[nt][ks][1]);
        #pragma unroll
        for (int mt = 0; mt < 2; mt++)
            #pragma unroll
            for (int nt = 0; nt < 4; nt++){
                s[nt][0] += gelu_fast(c[mt][nt][0] + prev[nt][0]) + gelu_fast(c[mt][nt][2] + prev[nt][0]);
                s[nt][1] += gelu_fast(c[mt][nt][1] + prev[nt][1]) + gelu_fast(c[mt][nt][3] + prev[nt][1]);
            }
    }

    #pragma unroll
    for (int off = 16; off >= 4; off >>= 1)
        #pragma unroll
        for (int nt = 0; nt < 4; nt++){
            s[nt][0] += __shfl_xor_sync(0xffffffff, s[nt][0], off);
            s[nt][1] += __shfl_xor_sync(0xffffffff, s[nt][1], off);
        }
    if (qrow == 0){
        #pragma unroll
        for (int nt = 0; nt < 4; nt++){
            int j = n0 + nt*8 + qk2;
            float v0 = s[nt][0] * (1.0f/256.0f);
            float v1 = s[nt][1] * (1.0f/256.0f);
            gbuf[j] = v0; gbuf[j+1] = v1;
            g_gctx[b*DM + j]     = v0;
            g_gctx[b*DM + j + 1] = v1;
        }
    }
    __syncthreads();

    if (warp == 0){
        float p[6] = {0,0,0,0,0,0};
        for (int k = lane; k < DM; k += 32){
            float g = gbuf[k];
            const float* w = Wr + k*NE;
            #pragma unroll
            for (int e = 0; e < 6; e++) p[e] = fmaf(g, w[e], p[e]);
        }
        #pragma unroll
        for (int off = 16; off; off >>= 1)
            #pragma unroll
            for (int e = 0; e < 6; e++) p[e] += __shfl_xor_sync(0xffffffff, p[e], off);
        if (lane == 0){
            float l[6], pr[6];
            #pragma unroll
            for (int e = 0; e < 6; e++) l[e] = p[e] + br[e];
            float m = l[0];
            #pragma unroll
            for (int e = 1; e < 6; e++) m = fmaxf(m, l[e]);
            float sv = 0.0f;
            #pragma unroll
            for (int e = 0; e < 6; e++){ pr[e] = expf(l[e] - m); sv += pr[e]; }
            float inv = 1.0f / sv;
            #pragma unroll
            for (int e = 0; e < 6; e++){ pr[e] *= inv; g_probs[b*NE + e] = pr[e]; }
            int pl = phase[b];
            int sel = pl + ((pr[pl+3] > pr[pl]) ? 3 : 0);
            g_sel[b] = sel;
            if (b < 4){
                #pragma unroll
                for (int e = 0; e < 6; e++){
                    int idx = atomicAdd(&g_cnt[e], 1);
                    g_list[e*512 + idx] = b;
                }
            } else {
                int idx = atomicAdd(&g_cnt[sel], 1);
                g_list[sel*512 + idx] = b;
            }
        }
    }
}

// ---------------- K3c: base via bf16 MMA, k-split x4, atomic accumulate ----------------
#define BAPAD 264
__global__ void __launch_bounds__(256, 2)
k_base(const float* __restrict__ b1_unused){
    extern __shared__ char smraw[];
    __nv_bfloat16* As = (__nv_bfloat16*)smraw;   // 32 x 264
    int* bl = (int*)(As + 32*BAPAD);             // 32

    int e = blockIdx.x, tile = blockIdx.y;
    int hs = blockIdx.z & 1;
    int kq = blockIdx.z >> 1;
    int n = g_cnt[e], s0 = tile*32;
    if (s0 >= n) return;
    int tid = threadIdx.x;

    if (tid < 32){
        int s = s0 + tid;
        bl[tid] = (s < n) ? g_list[e*512 + s] : g_list[e*512];
    }
    __syncthreads();

    {
        int r = tid >> 3, seg = tid & 7;
        int bb = bl[r];
        const float* srcbase = (kq < 2)
            ? (g_gctx + bb*512 + kq*256)
            : (g_temb + bb*512 + (kq - 2)*256);
        const float4* src = (const float4*)(srcbase + seg*32);
        __nv_bfloat16* dst = As + r*BAPAD + seg*32;
        #pragma unroll
        for (int i = 0; i < 8; i++){
            float4 v = src[i];
            *(__nv_bfloat162*)(dst + i*4    ) = __floats2bfloat162_rn(v.x, v.y);
            *(__nv_bfloat162*)(dst + i*4 + 2) = __floats2bfloat162_rn(v.z, v.w);
        }
    }
    __syncthreads();

    int warp = tid >> 5, lane = tid & 31;
    int qrow = lane >> 2;
    int qk2 = (lane & 3) * 2;
    int nb = hs*256 + warp*32;
    int hg0 = nb >> 3;
    const __nv_bfloat16* W1bE = c_W1b + (size_t)e*524288;

    float acc[2][4][4];
    #pragma unroll
    for (int mt = 0; mt < 2; mt++)
        #pragma unroll
        for (int nt = 0; nt < 4; nt++)
            #pragma unroll
            for (int r = 0; r < 4; r++) acc[mt][nt][r] = 0.0f;

    #pragma unroll
    for (int kc = 0; kc < 4; kc++){
        #pragma unroll
        for (int ks = 0; ks < 4; ks++){
            int kof = kc*64 + ks*16 + qk2;
            int kg = kq*16 + kc*4 + ks;
            unsigned a[2][4];
            #pragma unroll
            for (int mt = 0; mt < 2; mt++){
                const __nv_bfloat16* ap = As + (mt*16 + qrow)*BAPAD + kof;
                a[mt][0] = *(const unsigned*)(ap);
                a[mt][1] = *(const unsigned*)(ap + 8*BAPAD);
                a[mt][2] = *(const unsigned*)(ap + 8);
                a[mt][3] = *(const unsigned*)(ap + 8*BAPAD + 8);
            }
            #pragma unroll
            for (int nt = 0; nt < 4; nt++){
                const __nv_bfloat16* bp = W1bE + (size_t)((hg0 + nt)*64 + kg)*128 + qrow*16 + qk2;
                unsigned b0 = *(const unsigned*)(bp);
                unsigned b1v = *(const unsigned*)(bp + 8);
                mma16816(acc[0][nt], a[0], b0, b1v);
                mma16816(acc[1][nt], a[1], b0, b1v);
            }
        }
    }

    #pragma unroll
    for (int mt = 0; mt < 2; mt++){
        #pragma unroll
        for (int half = 0; half < 2; half++){
            int r = mt*16 + qrow + half*8;
            if (s0 + r < n){
                int bb = bl[r];
                float* dst = g_base + ((size_t)e*B + bb)*512;
                #pragma unroll
                for (int nt = 0; nt < 4; nt++){
                    int h = nb + nt*8 + qk2;
                    atomicAdd(&dst[h],     acc[mt][nt][half*2    ]);
                    atomicAdd(&dst[h + 1], acc[mt][nt][half*2 + 1]);
                }
            }
        }
    }
}

// ---------------- K4: expert MLP (b1 added at basev load) ----------------
__global__ void __launch_bounds__(128, 5)
k_expert(const float* __restrict__ fut, const float* __restrict__ eps,
         const int* __restrict__ t, const float* __restrict__ b2,
         const float* __restrict__ b1){
    extern __shared__ char smraw[];
    __nv_bfloat16* nzs = (__nv_bfloat16*)smraw;       // 32 x 72
    __nv_bfloat16* hss = nzs + 32*72;                 // 32 x 520
    float* basev = (float*)(hss + 32*520);            // 512
    __shared__ float red[4];

    int p2 = blockIdx.x;
    int p = p2 >> 1, mhalf = p2 & 1;
    int b, e;
    if (p < 24){ b = p / 6; e = p - b*6; }
    else       { b = p - 20; e = g_sel[p - 20]; }
    int tid = threadIdx.x;
    bool do_loss  = (e == g_sel[b]);
    bool do_store = (b < 4);

    float ab = g_ab[t[b]];
    float sa = sqrtf(ab), sb = sqrtf(1.0f - ab);

    {
        int r = tid >> 2, c0 = (tid & 3) * 16;
        int gr = mhalf*32 + r;
        const float4* f4 = (const float4*)(fut + (size_t)b*4096 + gr*64 + c0);
        const float4* e4 = (const float4*)(eps + (size_t)b*4096 + gr*64 + c0);
        __nv_bfloat16* dst = nzs + r*72 + c0;
        #pragma unroll
        for (int i = 0; i < 4; i++){
            float4 vf = f4[i], ve = e4[i];
            *(__nv_bfloat162*)(dst + i*4    ) = __floats2bfloat162_rn(fmaf(sa,vf.x,sb*ve.x), fmaf(sa,vf.y,sb*ve.y));
            *(__nv_bfloat162*)(dst + i*4 + 2) = __floats2bfloat162_rn(fmaf(sa,vf.z,sb*ve.z), fmaf(sa,vf.w,sb*ve.w));
        }
    }
    #pragma unroll
    for (int i = 0; i < 4; i++){
        int idx = tid + i*128;
        basev[idx] = g_base[((size_t)e*B + b)*512 + idx] + b1[e*512 + idx];
    }
    __syncthreads();

    int warp = tid >> 5, lane = tid & 31;
    int qrow = lane >> 2, qk2 = (lane & 3) * 2;

    // ---- phase1: warp owns 128 h-cols, M=32 local ----
    {
        int n0 = warp * 128;
        const __nv_bfloat16* W1nE = c_W1n + (size_t)e*32768;

        unsigned a[2][4][4];
        #pragma unroll
        for (int mt = 0; mt < 2; mt++)
            #pragma unroll
            for (int ks = 0; ks < 4; ks++){
                const __nv_bfloat16* ap = nzs + (mt*16 + qrow)*72 + ks*16 + qk2;
                a[mt][ks][0] = *(const unsigned*)(ap);
                a[mt][ks][1] = *(const unsigned*)(ap + 8*72);
                a[mt][ks][2] = *(const unsigned*)(ap + 8);
                a[mt][ks][3] = *(const unsigned*)(ap + 8*72 + 8);
            }

        #pragma unroll 4
        for (int nto = 0; nto < 16; nto++){
            int h8 = n0 + nto*8;
            int hg = warp*16 + nto;
            unsigned bfr[4][2];
            #pragma unroll
            for (int ks = 0; ks < 4; ks++){
                const __nv_bfloat16* bp = W1nE + (hg*4 + ks)*128 + qrow*16 + qk2;
                bfr[ks][0] = *(const unsigned*)(bp);
                bfr[ks][1] = *(const unsigned*)(bp + 8);
            }
            float c0v[2][4];
            #pragma unroll
            for (int mt = 0; mt < 2; mt++)
                #pragma unroll
                for (int r = 0; r < 4; r++) c0v[mt][r] = 0.0f;
            #pragma unroll
            for (int ks = 0; ks < 4; ks++){
                #pragma unroll
                for (int mt = 0; mt < 2; mt++)
                    mma16816(c0v[mt], a[mt][ks], bfr[ks][0], bfr[ks][1]);
            }
            int h = h8 + qk2;
            float ba0 = basev[h], ba1 = basev[h+1];
            #pragma unroll
            for (int mt = 0; mt < 2; mt++){
                int r = mt*16 + qrow;
                *(__nv_bfloat162*)(hss + r*520 + h) =
                    __floats2bfloat162_rn(gelu_fast(c0v[mt][0] + ba0), gelu_fast(c0v[mt][1] + ba1));
                *(__nv_bfloat162*)(hss + (r+8)*520 + h) =
                    __floats2bfloat162_rn(gelu_fast(c0v[mt][2] + ba0), gelu_fast(c0v[mt][3] + ba1));
            }
        }
    }
    __syncthreads();

    // ---- phase2: warp owns 16 f-cols, M=32 local, K=512 ----
    int f0 = warp * 16;
    const __nv_bfloat16* W2tE = c_W2t + (size_t)e*32768;

    float acc[2][2][4];
    #pragma unroll
    for (int mt = 0; mt < 2; mt++)
        #pragma unroll
        for (int nt = 0; nt < 2; nt++)
            #pragma unroll
            for (int r = 0; r < 4; r++) acc[mt][nt][r] = 0.0f;

    #pragma unroll 8
    for (int ks = 0; ks < 32; ks++){
        unsigned bfr[2][2];
        #pragma unroll
        for (int nt = 0; nt < 2; nt++){
            int fg = warp*2 + nt;
            const __nv_bfloat16* bp = W2tE + (fg*32 + ks)*128 + qrow*16 + qk2;
            bfr[nt][0] = *(const unsigned*)(bp);
            bfr[nt][1] = *(const unsigned*)(bp + 8);
        }
        #pragma unroll
        for (int mt = 0; mt < 2; mt++){
            const __nv_bfloat16* ap = hss + (mt*16 + qrow)*520 + ks*16 + qk2;
            unsigned a2[4];
            a2[0] = *(const unsigned*)(ap);
            a2[1] = *(const unsigned*)(ap + 8*520);
            a2[2] = *(const unsigned*)(ap + 8);
            a2[3] = *(const unsigned*)(ap + 8*520 + 8);
            mma16816(acc[mt][0], a2, bfr[0][0], bfr[0][1]);
            mma16816(acc[mt][1], a2, bfr[1][0], bfr[1][1]);
        }
    }

    float lsum = 0.0f;
    #pragma unroll
    for (int mt = 0; mt < 2; mt++){
        #pragma unroll
        for (int nt = 0; nt < 2; nt++){
            int fcol = f0 + nt*8 + qk2;
            float bb0 = b2[e*64 + fcol], bb1 = b2[e*64 + fcol + 1];
            #pragma unroll
            for (int h2 = 0; h2 < 2; h2++){
                int rg = mhalf*32 + mt*16 + qrow + h2*8;
                float o0 = acc[mt][nt][h2*2    ] + bb0;
                float o1 = acc[mt][nt][h2*2 + 1] + bb1;
                if (do_store){
                    float2 st; st.x = o0; st.y = o1;
                    *(float2*)&g_outsub[((e*4 + b)*64 + rg)*64 + fcol] = st;
                }
                if (do_loss){
                    float2 ev = *(const float2*)&eps[(size_t)b*4096 + rg*64 + fcol];
                    float d0 = o0 - ev.x, d1 = o1 - ev.y;
                    lsum += d0*d0 + d1*d1;
                }
            }
        }
    }

    if (do_loss){
        #pragma unroll
        for (int off = 16; off; off >>= 1) lsum += __shfl_xor_sync(0xffffffff, lsum, off);
        if (lane == 0) red[warp] = lsum;
        __syncthreads();
        if (tid == 0){
            float tot = red[0] + red[1] + red[2] + red[3];
            atomicAdd(&g_loss[b], tot * (1.0f/4096.0f));
        }
    }
}

// ---------------- K5: parallel final reduction + last-block scalar ----------------
#define FIN_BLKS 96
__global__ void k_final(float* __restrict__ out){
    int bid = blockIdx.x, tid = threadIdx.x;
    if (bid < 2){
        __shared__ float sh[13];
        if (tid < 13) sh[tid] = 0.0f;
        __syncthreads();
        const float PW[3] = {1.0f, 5.0f, 5.0f};
        int b = bid*256 + tid;
        int s = g_sel[b];
        atomicAdd(&sh[0], g_loss[b] * PW[s % 3]);
        atomicAdd(&sh[1 + s], 1.0f);
        #pragma unroll
        for (int e = 0; e < 6; e++) atomicAdd(&sh[7 + e], g_probs[b*NE + e]);
        __syncthreads();
        if (tid == 0) atomicAdd(&g_accL, sh[0]);
        if (tid < 6){
            atomicAdd(&g_cntF[tid],  sh[1 + tid]);
            atomicAdd(&g_psumE[tid], sh[7 + tid]);
        }
    } else {
        int nb = FIN_BLKS - 2;
        int idx0 = (bid - 2)*256 + tid;
        int stride = nb*256;
        const int pa[7] = {0,1,3,4,0,1,2};
        const int pb[7] = {1,2,4,5,3,4,5};
        float ch = 0.0f;
        for (int i = idx0; i < 16384; i += stride){
            #pragma unroll
            for (int q = 0; q < 7; q++){
                float d = g_outsub[pa[q]*16384 + i] - g_outsub[pb[q]*16384 + i];
                ch += d*d;
            }
        }
        float smv = 0.0f;
        for (int i = idx0; i < 96768; i += stride){
            int e  = i / 16128; int r  = i - e*16128;
            int s  = r / 4032;  int r2 = r - s*4032;
            int idx = (e*4 + s)*4096 + r2;
            float d = g_outsub[idx + 64] - g_outsub[idx];
            smv += d*d;
        }
        #pragma unroll
        for (int off = 16; off; off >>= 1){
            ch  += __shfl_xor_sync(0xffffffff, ch,  off);
            smv += __shfl_xor_sync(0xffffffff, smv, off);
        }
        if ((tid & 31) == 0){
            atomicAdd(&g_accC, ch);
            atomicAdd(&g_accS, smv);
        }
    }

    __syncthreads();
    __shared__ bool amLast;
    if (tid == 0){
        __threadfence();
        unsigned old = atomicAdd(&g_finDone, 1u);
        amLast = (old == FIN_BLKS - 1);
    }
    __syncthreads();
    if (amLast && tid == 0){
        __threadfence();
        float lb = 0.0f;
        #pragma unroll
        for (int e = 0; e < 6; e++)
            lb += (g_cntF[e] / 512.0f) * (g_psumE[e] / 512.0f);
        out[0] = g_accL / 512.0f
               + 0.01f * (g_accC / 16384.0f + 0.5f * g_accS / 16128.0f)
               + 0.06f * lb;
    }
}

// ---------------- launch ----------------
extern "C" void kernel_launch(void* const* d_in, const int* in_sizes, int n_in,
                              void* d_out, int out_size){
    const float* obs  = (const float*)d_in[0];
    const float* fut  = (const float*)d_in[1];
    const float* sc   = (const float*)d_in[2];
    const float* eps  = (const float*)d_in[3];
    const int*   phase= (const int*)  d_in[4];
    const int*   t    = (const int*)  d_in[5];
    const float* Wenc = (const float*)d_in[6];
    const float* benc = (const float*)d_in[7];
    const float* Wstat= (const float*)d_in[8];
    const float* Wr   = (const float*)d_in[9];
    const float* br   = (const float*)d_in[10];
    const float* W1   = (const float*)d_in[11];
    const float* b1   = (const float*)d_in[12];
    const float* W2   = (const float*)d_in[13];
    const float* b2   = (const float*)d_in[14];

    const int SMEM_CTX  = 256*APAD*2 + 2*512*4;            // 40,960 B
    const int SMEM_BASE = 32*BAPAD*2 + 128;                // 17,024 B
    const int SMEM_EXP  = (32*72 + 32*520)*2 + 512*4;      // 39,936 B

    static bool once = false;
    static cudaStream_t s2;
    static cudaEvent_t evFork, evJoin;
    if (!once){
        cudaFuncSetAttribute(k_ctx_fused, cudaFuncAttributeMaxDynamicSharedMemorySize, SMEM_CTX);
        cudaFuncSetAttribute(k_base,      cudaFuncAttributeMaxDynamicSharedMemorySize, SMEM_BASE);
        cudaFuncSetAttribute(k_expert,    cudaFuncAttributeMaxDynamicSharedMemorySize, SMEM_EXP);
        cudaStreamCreateWithFlags(&s2, cudaStreamNonBlocking);
        cudaEventCreateWithFlags(&evFork, cudaEventDisableTiming);
        cudaEventCreateWithFlags(&evJoin, cudaEventDisableTiming);
        once = true;
    }

    k_init2<<<5, 256>>>(Wenc);

    cudaEventRecord(evFork, 0);
    cudaStreamWaitEvent(s2, evFork, 0);
    k_prep<<<4032, 256, 0, s2>>>(t, W1, W2);
    cudaEventRecord(evJoin, s2);

    k_ctx_fused<<<B, 512, SMEM_CTX>>>(obs, sc, benc, Wstat, Wr, br, phase);

    cudaStreamWaitEvent(0, evJoin, 0);

    k_base  <<<dim3(NE, 16, 8), 256, SMEM_BASE>>>(b1);
    k_expert<<<2*NPAIR, 128, SMEM_EXP>>>(fut, eps, t, b2, b1);
    k_final <<<FIN_BLKS, 256>>>((float*)d_out);
}

// round 15
// speedup vs baseline: 1.5451x; 1.0219x over previous
#include <cuda_runtime.h>
#include <cuda_bf16.h>
#include <math.h>

#define B   512
#define TP  256
#define DM  512
#define DS  32
#define NE  6
#define NPAIR 532

// ---------------- device scratch ----------------
__device__ float g_ab[1000];
__device__ float g_gctx[B*DM];
__device__ float g_temb[B*DM];
__device__ float g_probs[B*NE];
__device__ int   g_sel[B];
__device__ float g_loss[B];
__device__ float g_outsub[NE*4*64*64];
__device__ int   g_cnt[NE];
__device__ int   g_list[NE*512];
__device__ float g_base[NE*B*512];
// fragment-tiled bf16 weights: each n8 x k16 tile contiguous as [r(8)][kk(16)] = 128 elems
__device__ __nv_bfloat16 c_Wenc[DM*64];                 // [ng 64][kg 4][128]
__device__ __nv_bfloat16 c_W1n[NE*512*64];              // [e][hg 64][kg 4][128]
__device__ __nv_bfloat16 c_W1b[(size_t)NE*512*1024];    // [e][hg 64][kg 64][128]
__device__ __nv_bfloat16 c_W2t[NE*64*512];              // [e][fg 8][kg 32][128]
__device__ float g_accL, g_accC, g_accS;
__device__ float g_psumE[NE];
__device__ float g_cntF[NE];
__device__ unsigned g_finDone;

// lean gelu: u = x*(c1 + c1*c2*s), y = 0.5x + 0.5x*tanh(u)  (5 ops + 1 MUFU)
__device__ __forceinline__ float gelu_fast(float x){
    float s = x*x;
    float t = fmaf(s, 0.035677408136f, 0.7978845608f);   // c1*c2, c1
    float u = x*t;
    float th;
    asm("tanh.approx.f32 %0, %1;" : "=f"(th) : "f"(u));
    float hx = 0.5f*x;
    return fmaf(hx, th, hx);
}

__device__ __forceinline__ void mma16816(float* c, const unsigned* a, unsigned b0, unsigned b1){
    asm("mma.sync.aligned.m16n8k16.row.col.f32.bf16.bf16.f32 "
        "{%0,%1,%2,%3}, {%4,%5,%6,%7}, {%8,%9}, {%0,%1,%2,%3};"
        : "+f"(c[0]), "+f"(c[1]), "+f"(c[2]), "+f"(c[3])
        : "r"(a[0]), "r"(a[1]), "r"(a[2]), "r"(a[3]), "r"(b0), "r"(b1));
}

// ---------------- K0: init scalars + Wenc convert (tiled) ----------------
__global__ void k_init2(const float* __restrict__ Wenc){
    int tid = threadIdx.x;
    if (blockIdx.x == 0){
        if (tid < NE){ g_cnt[tid] = 0; g_psumE[tid] = 0.0f; g_cntF[tid] = 0.0f; }
        if (tid == 6){ g_accL = 0.0f; g_accC = 0.0f; g_accS = 0.0f; g_finDone = 0u; }
        g_loss[tid] = 0.0f;
        g_loss[tid + 256] = 0.0f;
        if (tid == 0){
            float ab = 1.0f;
            const float step = (0.02f - 0.0001f) / 999.0f;
            for (int i = 0; i < 1000; i++){
                float beta = 0.0001f + step * (float)i;
                ab *= (1.0f - beta);
                g_ab[i] = ab;
            }
        }
    } else {
        int gid = (blockIdx.x - 1)*256 + tid;   // 1024 threads
        int n = gid >> 1, kh = (gid & 1) * 32;
        int ng = n >> 3, r = n & 7;
        #pragma unroll
        for (int i = 0; i < 32; i++){
            int k = kh + i;
            int kg = k >> 4, kk = k & 15;
            c_Wenc[(ng*4 + kg)*128 + r*16 + kk] = __float2bfloat16_rn(Wenc[k*DM + n]);
        }
    }
}

// ---------------- K1: merged prep (W1, W2 converts + temb + g_base zero) ----------------
__global__ void k_prep(const int* __restrict__ t,
                       const float* __restrict__ W1, const float* __restrict__ W2){
    __shared__ float sm[32][33];
    int bid = blockIdx.x;
    int tid = threadIdx.x;

    if (bid < 3264){                       // W1 convert
        int e = bid / 544, rem = bid - e*544;
        int kt = rem >> 4, ht = rem & 15;
        int i = tid >> 3, j4 = (tid & 7) * 4;
        float4 v = *(const float4*)&W1[((size_t)e*1088 + kt*32 + i)*512 + ht*32 + j4];
        sm[i][j4] = v.x; sm[i][j4+1] = v.y; sm[i][j4+2] = v.z; sm[i][j4+3] = v.w;
        __syncthreads();
        int h = ht*32 + i;
        int k = kt*32 + j4;
        __nv_bfloat162 p0 = __floats2bfloat162_rn(sm[j4][i],   sm[j4+1][i]);
        __nv_bfloat162 p1 = __floats2bfloat162_rn(sm[j4+2][i], sm[j4+3][i]);
        int hg = h >> 3, r = h & 7;
        __nv_bfloat16* dst;
        if (kt < 2){
            int kg = k >> 4, kk = k & 15;
            dst = c_W1n + (size_t)e*32768 + (hg*4 + kg)*128 + r*16 + kk;
        } else {
            int kp = k - 64;
            int kg = kp >> 4, kk = kp & 15;
            dst = c_W1b + (size_t)e*524288 + (size_t)(hg*64 + kg)*128 + r*16 + kk;
        }
        *(__nv_bfloat162*)dst       = p0;
        *(__nv_bfloat162*)(dst + 2) = p1;
    } else if (bid < 3456){                // W2 convert
        int idx2 = bid - 3264;
        int e = idx2 >> 5, rem = idx2 & 31;
        int ht = rem >> 1, ft = rem & 1;
        int i = tid >> 3, j4 = (tid & 7) * 4;
        float4 v = *(const float4*)&W2[((size_t)e*512 + ht*32 + i)*64 + ft*32 + j4];
        sm[i][j4] = v.x; sm[i][j4+1] = v.y; sm[i][j4+2] = v.z; sm[i][j4+3] = v.w;
        __syncthreads();
        int f = ft*32 + i;
        int h = ht*32 + j4;
        __nv_bfloat162 p0 = __floats2bfloat162_rn(sm[j4][i],   sm[j4+1][i]);
        __nv_bfloat162 p1 = __floats2bfloat162_rn(sm[j4+2][i], sm[j4+3][i]);
        int fg = f >> 3, r = f & 7;
        int kg = h >> 4, kk = h & 15;
        __nv_bfloat16* dst = c_W2t + (size_t)e*32768 + (fg*32 + kg)*128 + r*16 + kk;
        *(__nv_bfloat162*)dst       = p0;
        *(__nv_bfloat162*)(dst + 2) = p1;
    } else if (bid < 3968){                // temb
        int b = bid - 3456;
        float tv = (float)t[b];
        for (int j = tid; j < DM; j += 256){
            int i = (j < 256) ? j : (j - 256);
            float freq = expf(-9.210340371976184f * (float)i / 256.0f);
            float a = tv * freq;
            g_temb[b*DM + j] = (j < 256) ? sinf(a) : cosf(a);
        }
    } else {                               // zero g_base
        int zb = bid - 3968;
        float4* p = (float4*)g_base;
        const int total4 = NE*B*512/4;     // 393216
        for (int i = zb*256 + tid; i < total4; i += 64*256){
            float4 z; z.x = 0.0f; z.y = 0.0f; z.z = 0.0f; z.w = 0.0f;
            p[i] = z;
        }
    }
}

// ---------------- K2: fused ctx GEMM + router ----------------
#define APAD 72
__global__ void __launch_bounds__(512, 1)
k_ctx_fused(const float* __restrict__ obs, const float* __restrict__ sc,
            const float* __restrict__ benc, const float* __restrict__ Wstat,
            const float* __restrict__ Wr, const float* __restrict__ br,
            const int* __restrict__ phase){
    extern __shared__ char smraw[];
    __nv_bfloat16* As = (__nv_bfloat16*)smraw;
    float* pre  = (float*)(As + 256*APAD);
    float* gbuf = pre + 512;

    int b = blockIdx.x;
    int tid = threadIdx.x;

    {
        int row = tid >> 1;
        int c0  = (tid & 1) * 32;
        const float4* src = (const float4*)(obs + (size_t)b*TP*64 + row*64 + c0);
        __nv_bfloat16* arow = As + row*APAD + c0;
        #pragma unroll
        for (int i = 0; i < 8; i++){
            float4 v = src[i];
            *(__nv_bfloat162*)(arow + i*4    ) = __floats2bfloat162_rn(v.x, v.y);
            *(__nv_bfloat162*)(arow + i*4 + 2) = __floats2bfloat162_rn(v.z, v.w);
        }
    }
    {
        float acc = benc[tid];
        #pragma unroll
        for (int k = 0; k < 32; k++) acc = fmaf(sc[b*DS + k], Wstat[k*DM + tid], acc);
        pre[tid] = acc;
    }
    __syncthreads();

    int warp = tid >> 5, lane = tid & 31;
    int qrow = lane >> 2, qk2 = (lane & 3) * 2;
    int n0 = warp * 32;

    unsigned bfr[4][4][2];
    #pragma unroll
    for (int nt = 0; nt < 4; nt++)
        #pragma unroll
        for (int ks = 0; ks < 4; ks++){
            const __nv_bfloat16* bp = c_Wenc + ((warp*4 + nt)*4 + ks)*128 + qrow*16 + qk2;
            bfr[nt][ks][0] = *(const unsigned*)(bp);
            bfr[nt][ks][1] = *(const unsigned*)(bp + 8);
        }
    float prev[4][2];
    #pragma unroll
    for (int nt = 0; nt < 4; nt++){
        prev[nt][0] = pre[n0 + nt*8 + qk2];
        prev[nt][1] = pre[n0 + nt*8 + qk2 + 1];
    }

    float s[4][2];
    #pragma unroll
    for (int nt = 0; nt < 4; nt++){ s[nt][0] = 0.0f; s[nt][1] = 0.0f; }

    #pragma unroll 2
    for (int mc = 0; mc < 8; mc++){
        unsigned a[2][4][4];
        #pragma unroll
        for (int mt = 0; mt < 2; mt++)
            #pragma unroll
            for (int ks = 0; ks < 4; ks++){
                const __nv_bfloat16* ap = As + (mc*32 + mt*16 + qrow)*APAD + ks*16 + qk2;
                a[mt][ks][0] = *(const unsigned*)(ap);
                a[mt][ks][1] = *(const unsigned*)(ap + 8*APAD);
                a[mt][ks][2] = *(const unsigned*)(ap + 8);
                a[mt][ks][3] = *(const unsigned*)(ap + 8*APAD + 8);
            }
        float c[2][4][4];
        #pragma unroll
        for (int mt = 0; mt < 2; mt++)
            #pragma unroll
            for (int nt = 0; nt < 4; nt++){
                c[mt][nt][0] = prev[nt][0];   // bias pre-loaded into accumulator
                c[mt][nt][1] = prev[nt][1];
                c[mt][nt][2] = prev[nt][0];
                c[mt][nt][3] = prev[nt][1];
            }
        #pragma unroll
        for (int ks = 0; ks < 4; ks++)
            #pragma unroll
            for (int mt = 0; mt < 2; mt++)
                #pragma unroll
                for (int nt = 0; nt < 4; nt++)
                    mma16816(c[mt][nt], a[mt][ks], bfr[nt][ks][0], bfr[nt][ks][1]);
        #pragma unroll
        for (int mt = 0; mt < 2; mt++)
            #pragma unroll
            for (int nt = 0; nt < 4; nt++){
                s[nt][0] += gelu_fast(c[mt][nt][0]) + gelu_fast(c[mt][nt][2]);
                s[nt][1] += gelu_fast(c[mt][nt][1]) + gelu_fast(c[mt][nt][3]);
            }
    }

    #pragma unroll
    for (int off = 16; off >= 4; off >>= 1)
        #pragma unroll
        for (int nt = 0; nt < 4; nt++){
            s[nt][0] += __shfl_xor_sync(0xffffffff, s[nt][0], off);
            s[nt][1] += __shfl_xor_sync(0xffffffff, s[nt][1], off);
        }
    if (qrow == 0){
        #pragma unroll
        for (int nt = 0; nt < 4; nt++){
            int j = n0 + nt*8 + qk2;
            float v0 = s[nt][0] * (1.0f/256.0f);
            float v1 = s[nt][1] * (1.0f/256.0f);
            gbuf[j] = v0; gbuf[j+1] = v1;
            g_gctx[b*DM + j]     = v0;
            g_gctx[b*DM + j + 1] = v1;
        }
    }
    __syncthreads();

    if (warp == 0){
        float p[6] = {0,0,0,0,0,0};
        for (int k = lane; k < DM; k += 32){
            float g = gbuf[k];
            const float* w = Wr + k*NE;
            #pragma unroll
            for (int e = 0; e < 6; e++) p[e] = fmaf(g, w[e], p[e]);
        }
        #pragma unroll
        for (int off = 16; off; off >>= 1)
            #pragma unroll
            for (int e = 0; e < 6; e++) p[e] += __shfl_xor_sync(0xffffffff, p[e], off);
        if (lane == 0){
            float l[6], pr[6];
            #pragma unroll
            for (int e = 0; e < 6; e++) l[e] = p[e] + br[e];
            float m = l[0];
            #pragma unroll
            for (int e = 1; e < 6; e++) m = fmaxf(m, l[e]);
            float sv = 0.0f;
            #pragma unroll
            for (int e = 0; e < 6; e++){ pr[e] = expf(l[e] - m); sv += pr[e]; }
            float inv = 1.0f / sv;
            #pragma unroll
            for (int e = 0; e < 6; e++){ pr[e] *= inv; g_probs[b*NE + e] = pr[e]; }
            int pl = phase[b];
            int sel = pl + ((pr[pl+3] > pr[pl]) ? 3 : 0);
            g_sel[b] = sel;
            if (b < 4){
                #pragma unroll
                for (int e = 0; e < 6; e++){
                    int idx = atomicAdd(&g_cnt[e], 1);
                    g_list[e*512 + idx] = b;
                }
            } else {
                int idx = atomicAdd(&g_cnt[sel], 1);
                g_list[sel*512 + idx] = b;
            }
        }
    }
}

// ---------------- K3c: base via bf16 MMA, k-split x8 (z=16), atomic accumulate ----------------
#define BAPAD 136
__global__ void __launch_bounds__(256, 2)
k_base(const float* __restrict__ b1_unused){
    extern __shared__ char smraw[];
    __nv_bfloat16* As = (__nv_bfloat16*)smraw;   // 32 x 136 (128 k-cols + pad)
    int* bl = (int*)(As + 32*BAPAD);             // 32

    int e = blockIdx.x, tile = blockIdx.y;
    int hs = blockIdx.z & 1;       // h-half: 256 cols each
    int kq = blockIdx.z >> 1;      // k-chunk: 0..7 (128 k each)
    int n = g_cnt[e], s0 = tile*32;
    if (s0 >= n) return;
    int tid = threadIdx.x;

    if (tid < 32){
        int s = s0 + tid;
        bl[tid] = (s < n) ? g_list[e*512 + s] : g_list[e*512];
    }
    __syncthreads();

    {   // load 32 rows x 128 cols of (gctx|temb) k-chunk
        int r = tid >> 3, seg = tid & 7;   // seg: 16-col group
        int bb = bl[r];
        const float* srcbase = (kq < 4)
            ? (g_gctx + bb*512 + kq*128)
            : (g_temb + bb*512 + (kq - 4)*128);
        const float4* src = (const float4*)(srcbase + seg*16);
        __nv_bfloat16* dst = As + r*BAPAD + seg*16;
        #pragma unroll
        for (int i = 0; i < 4; i++){
            float4 v = src[i];
            *(__nv_bfloat162*)(dst + i*4    ) = __floats2bfloat162_rn(v.x, v.y);
            *(__nv_bfloat162*)(dst + i*4 + 2) = __floats2bfloat162_rn(v.z, v.w);
        }
    }
    __syncthreads();

    int warp = tid >> 5, lane = tid & 31;
    int qrow = lane >> 2;
    int qk2 = (lane & 3) * 2;
    int nb = hs*256 + warp*32;
    int hg0 = nb >> 3;
    const __nv_bfloat16* W1bE = c_W1b + (size_t)e*524288;

    float acc[2][4][4];
    #pragma unroll
    for (int mt = 0; mt < 2; mt++)
        #pragma unroll
        for (int nt = 0; nt < 4; nt++)
            #pragma unroll
            for (int r = 0; r < 4; r++) acc[mt][nt][r] = 0.0f;

    #pragma unroll
    for (int kc = 0; kc < 2; kc++){
        #pragma unroll
        for (int ks = 0; ks < 4; ks++){
            int kof = kc*64 + ks*16 + qk2;
            int kg = kq*8 + kc*4 + ks;
            unsigned a[2][4];
            #pragma unroll
            for (int mt = 0; mt < 2; mt++){
                const __nv_bfloat16* ap = As + (mt*16 + qrow)*BAPAD + kof;
                a[mt][0] = *(const unsigned*)(ap);
                a[mt][1] = *(const unsigned*)(ap + 8*BAPAD);
                a[mt][2] = *(const unsigned*)(ap + 8);
                a[mt][3] = *(const unsigned*)(ap + 8*BAPAD + 8);
            }
            #pragma unroll
            for (int nt = 0; nt < 4; nt++){
                const __nv_bfloat16* bp = W1bE + (size_t)((hg0 + nt)*64 + kg)*128 + qrow*16 + qk2;
                unsigned b0 = *(const unsigned*)(bp);
                unsigned b1v = *(const unsigned*)(bp + 8);
                mma16816(acc[0][nt], a[0], b0, b1v);
                mma16816(acc[1][nt], a[1], b0, b1v);
            }
        }
    }

    #pragma unroll
    for (int mt = 0; mt < 2; mt++){
        #pragma unroll
        for (int half = 0; half < 2; half++){
            int r = mt*16 + qrow + half*8;
            if (s0 + r < n){
                int bb = bl[r];
                float* dst = g_base + ((size_t)e*B + bb)*512;
                #pragma unroll
                for (int nt = 0; nt < 4; nt++){
                    int h = nb + nt*8 + qk2;
                    atomicAdd(&dst[h],     acc[mt][nt][half*2    ]);
                    atomicAdd(&dst[h + 1], acc[mt][nt][half*2 + 1]);
                }
            }
        }
    }
}

// ---------------- K4: expert MLP ----------------
__global__ void __launch_bounds__(128, 5)
k_expert(const float* __restrict__ fut, const float* __restrict__ eps,
         const int* __restrict__ t, const float* __restrict__ b2,
         const float* __restrict__ b1){
    extern __shared__ char smraw[];
    __nv_bfloat16* nzs = (__nv_bfloat16*)smraw;       // 32 x 72
    __nv_bfloat16* hss = nzs + 32*72;                 // 32 x 520
    float* basev = (float*)(hss + 32*520);            // 512
    __shared__ float red[4];

    int p2 = blockIdx.x;
    int p = p2 >> 1, mhalf = p2 & 1;
    int b, e;
    if (p < 24){ b = p / 6; e = p - b*6; }
    else       { b = p - 20; e = g_sel[p - 20]; }
    int tid = threadIdx.x;
    bool do_loss  = (e == g_sel[b]);
    bool do_store = (b < 4);

    float ab = g_ab[t[b]];
    float sa = sqrtf(ab), sb = sqrtf(1.0f - ab);

    {
        int r = tid >> 2, c0 = (tid & 3) * 16;
        int gr = mhalf*32 + r;
        const float4* f4 = (const float4*)(fut + (size_t)b*4096 + gr*64 + c0);
        const float4* e4 = (const float4*)(eps + (size_t)b*4096 + gr*64 + c0);
        __nv_bfloat16* dst = nzs + r*72 + c0;
        #pragma unroll
        for (int i = 0; i < 4; i++){
            float4 vf = f4[i], ve = e4[i];
            *(__nv_bfloat162*)(dst + i*4    ) = __floats2bfloat162_rn(fmaf(sa,vf.x,sb*ve.x), fmaf(sa,vf.y,sb*ve.y));
            *(__nv_bfloat162*)(dst + i*4 + 2) = __floats2bfloat162_rn(fmaf(sa,vf.z,sb*ve.z), fmaf(sa,vf.w,sb*ve.w));
        }
    }
    #pragma unroll
    for (int i = 0; i < 4; i++){
        int idx = tid + i*128;
        basev[idx] = g_base[((size_t)e*B + b)*512 + idx] + b1[e*512 + idx];
    }
    __syncthreads();

    int warp = tid >> 5, lane = tid & 31;
    int qrow = lane >> 2, qk2 = (lane & 3) * 2;

    // ---- phase1: warp owns 128 h-cols, M=32 local ----
    {
        int n0 = warp * 128;
        const __nv_bfloat16* W1nE = c_W1n + (size_t)e*32768;

        unsigned a[2][4][4];
        #pragma unroll
        for (int mt = 0; mt < 2; mt++)
            #pragma unroll
            for (int ks = 0; ks < 4; ks++){
                const __nv_bfloat16* ap = nzs + (mt*16 + qrow)*72 + ks*16 + qk2;
                a[mt][ks][0] = *(const unsigned*)(ap);
                a[mt][ks][1] = *(const unsigned*)(ap + 8*72);
                a[mt][ks][2] = *(const unsigned*)(ap + 8);
                a[mt][ks][3] = *(const unsigned*)(ap + 8*72 + 8);
            }

        #pragma unroll 4
        for (int nto = 0; nto < 16; nto++){
            int h8 = n0 + nto*8;
            int hg = warp*16 + nto;
            unsigned bfr[4][2];
            #pragma unroll
            for (int ks = 0; ks < 4; ks++){
                const __nv_bfloat16* bp = W1nE + (hg*4 + ks)*128 + qrow*16 + qk2;
                bfr[ks][0] = *(const unsigned*)(bp);
                bfr[ks][1] = *(const unsigned*)(bp + 8);
            }
            int h = h8 + qk2;
            float ba0 = basev[h], ba1 = basev[h+1];
            float c0v[2][4];
            #pragma unroll
            for (int mt = 0; mt < 2; mt++){
                c0v[mt][0] = ba0; c0v[mt][1] = ba1;   // bias pre-loaded
                c0v[mt][2] = ba0; c0v[mt][3] = ba1;
            }
            #pragma unroll
            for (int ks = 0; ks < 4; ks++){
                #pragma unroll
                for (int mt = 0; mt < 2; mt++)
                    mma16816(c0v[mt], a[mt][ks], bfr[ks][0], bfr[ks][1]);
            }
            #pragma unroll
            for (int mt = 0; mt < 2; mt++){
                int r = mt*16 + qrow;
                *(__nv_bfloat162*)(hss + r*520 + h) =
                    __floats2bfloat162_rn(gelu_fast(c0v[mt][0]), gelu_fast(c0v[mt][1]));
                *(__nv_bfloat162*)(hss + (r+8)*520 + h) =
                    __floats2bfloat162_rn(gelu_fast(c0v[mt][2]), gelu_fast(c0v[mt][3]));
            }
        }
    }
    __syncthreads();

    // ---- phase2: warp owns 16 f-cols, M=32 local, K=512 ----
    int f0 = warp * 16;
    const __nv_bfloat16* W2tE = c_W2t + (size_t)e*32768;

    float acc[2][2][4];
    #pragma unroll
    for (int nt = 0; nt < 2; nt++){
        int fcol = f0 + nt*8 + qk2;
        float bb0 = b2[e*64 + fcol], bb1 = b2[e*64 + fcol + 1];
        #pragma unroll
        for (int mt = 0; mt < 2; mt++){
            acc[mt][nt][0] = bb0; acc[mt][nt][1] = bb1;   // bias pre-loaded
            acc[mt][nt][2] = bb0; acc[mt][nt][3] = bb1;
        }
    }

    #pragma unroll 8
    for (int ks = 0; ks < 32; ks++){
        unsigned bfr[2][2];
        #pragma unroll
        for (int nt = 0; nt < 2; nt++){
            int fg = warp*2 + nt;
            const __nv_bfloat16* bp = W2tE + (fg*32 + ks)*128 + qrow*16 + qk2;
            bfr[nt][0] = *(const unsigned*)(bp);
            bfr[nt][1] = *(const unsigned*)(bp + 8);
        }
        #pragma unroll
        for (int mt = 0; mt < 2; mt++){
            const __nv_bfloat16* ap = hss + (mt*16 + qrow)*520 + ks*16 + qk2;
            unsigned a2[4];
            a2[0] = *(const unsigned*)(ap);
            a2[1] = *(const unsigned*)(ap + 8*520);
            a2[2] = *(const unsigned*)(ap + 8);
            a2[3] = *(const unsigned*)(ap + 8*520 + 8);
            mma16816(acc[mt][0], a2, bfr[0][0], bfr[0][1]);
            mma16816(acc[mt][1], a2, bfr[1][0], bfr[1][1]);
        }
    }

    float lsum = 0.0f;
    #pragma unroll
    for (int mt = 0; mt < 2; mt++){
        #pragma unroll
        for (int nt = 0; nt < 2; nt++){
            int fcol = f0 + nt*8 + qk2;
            #pragma unroll
            for (int h2 = 0; h2 < 2; h2++){
                int rg = mhalf*32 + mt*16 + qrow + h2*8;
                float o0 = acc[mt][nt][h2*2    ];
                float o1 = acc[mt][nt][h2*2 + 1];
                if (do_store){
                    float2 st; st.x = o0; st.y = o1;
                    *(float2*)&g_outsub[((e*4 + b)*64 + rg)*64 + fcol] = st;
                }
                if (do_loss){
                    float2 ev = *(const float2*)&eps[(size_t)b*4096 + rg*64 + fcol];
                    float d0 = o0 - ev.x, d1 = o1 - ev.y;
                    lsum += d0*d0 + d1*d1;
                }
            }
        }
    }

    if (do_loss){
        #pragma unroll
        for (int off = 16; off; off >>= 1) lsum += __shfl_xor_sync(0xffffffff, lsum, off);
        if (lane == 0) red[warp] = lsum;
        __syncthreads();
        if (tid == 0){
            float tot = red[0] + red[1] + red[2] + red[3];
            atomicAdd(&g_loss[b], tot * (1.0f/4096.0f));
        }
    }
}

// ---------------- K5: parallel final reduction + last-block scalar ----------------
#define FIN_BLKS 96
__global__ void k_final(float* __restrict__ out){
    int bid = blockIdx.x, tid = threadIdx.x;
    if (bid < 2){
        __shared__ float sh[13];
        if (tid < 13) sh[tid] = 0.0f;
        __syncthreads();
        const float PW[3] = {1.0f, 5.0f, 5.0f};
        int b = bid*256 + tid;
        int s = g_sel[b];
        atomicAdd(&sh[0], g_loss[b] * PW[s % 3]);
        atomicAdd(&sh[1 + s], 1.0f);
        #pragma unroll
        for (int e = 0; e < 6; e++) atomicAdd(&sh[7 + e], g_probs[b*NE + e]);
        __syncthreads();
        if (tid == 0) atomicAdd(&g_accL, sh[0]);
        if (tid < 6){
            atomicAdd(&g_cntF[tid],  sh[1 + tid]);
            atomicAdd(&g_psumE[tid], sh[7 + tid]);
        }
    } else {
        int nb = FIN_BLKS - 2;
        int idx0 = (bid - 2)*256 + tid;
        int stride = nb*256;
        const int pa[7] = {0,1,3,4,0,1,2};
        const int pb[7] = {1,2,4,5,3,4,5};
        float ch = 0.0f;
        for (int i = idx0; i < 16384; i += stride){
            #pragma unroll
            for (int q = 0; q < 7; q++){
                float d = g_outsub[pa[q]*16384 + i] - g_outsub[pb[q]*16384 + i];
                ch += d*d;
            }
        }
        float smv = 0.0f;
        for (int i = idx0; i < 96768; i += stride){
            int e  = i / 16128; int r  = i - e*16128;
            int s  = r / 4032;  int r2 = r - s*4032;
            int idx = (e*4 + s)*4096 + r2;
            float d = g_outsub[idx + 64] - g_outsub[idx];
            smv += d*d;
        }
        #pragma unroll
        for (int off = 16; off; off >>= 1){
            ch  += __shfl_xor_sync(0xffffffff, ch,  off);
            smv += __shfl_xor_sync(0xffffffff, smv, off);
        }
        if ((tid & 31) == 0){
            atomicAdd(&g_accC, ch);
            atomicAdd(&g_accS, smv);
        }
    }

    __syncthreads();
    __shared__ bool amLast;
    if (tid == 0){
        __threadfence();
        unsigned old = atomicAdd(&g_finDone, 1u);
        amLast = (old == FIN_BLKS - 1);
    }
    __syncthreads();
    if (amLast && tid == 0){
        __threadfence();
        float lb = 0.0f;
        #pragma unroll
        for (int e = 0; e < 6; e++)
            lb += (g_cntF[e] / 512.0f) * (g_psumE[e] / 512.0f);
        out[0] = g_accL / 512.0f
               + 0.01f * (g_accC / 16384.0f + 0.5f * g_accS / 16128.0f)
               + 0.06f * lb;
    }
}

// ---------------- launch ----------------
extern "C" void kernel_launch(void* const* d_in, const int* in_sizes, int n_in,
                              void* d_out, int out_size){
    const float* obs  = (const float*)d_in[0];
    const float* fut  = (const float*)d_in[1];
    const float* sc   = (const float*)d_in[2];
    const float* eps  = (const float*)d_in[3];
    const int*   phase= (const int*)  d_in[4];
    const int*   t    = (const int*)  d_in[5];
    const float* Wenc = (const float*)d_in[6];
    const float* benc = (const float*)d_in[7];
    const float* Wstat= (const float*)d_in[8];
    const float* Wr   = (const float*)d_in[9];
    const float* br   = (const float*)d_in[10];
    const float* W1   = (const float*)d_in[11];
    const float* b1   = (const float*)d_in[12];
    const float* W2   = (const float*)d_in[13];
    const float* b2   = (const float*)d_in[14];

    const int SMEM_CTX  = 256*APAD*2 + 2*512*4;            // 40,960 B
    const int SMEM_BASE = 32*BAPAD*2 + 128;                // 8,832 B
    const int SMEM_EXP  = (32*72 + 32*520)*2 + 512*4;      // 39,936 B

    static bool once = false;
    static cudaStream_t s2;
    static cudaEvent_t evFork, evJoin;
    if (!once){
        cudaFuncSetAttribute(k_ctx_fused, cudaFuncAttributeMaxDynamicSharedMemorySize, SMEM_CTX);
        cudaFuncSetAttribute(k_base,      cudaFuncAttributeMaxDynamicSharedMemorySize, SMEM_BASE);
        cudaFuncSetAttribute(k_expert,    cudaFuncAttributeMaxDynamicSharedMemorySize, SMEM_EXP);
        cudaStreamCreateWithFlags(&s2, cudaStreamNonBlocking);
        cudaEventCreateWithFlags(&evFork, cudaEventDisableTiming);
        cudaEventCreateWithFlags(&evJoin, cudaEventDisableTiming);
        once = true;
    }

    k_init2<<<5, 256>>>(Wenc);

    cudaEventRecord(evFork, 0);
    cudaStreamWaitEvent(s2, evFork, 0);
    k_prep<<<4032, 256, 0, s2>>>(t, W1, W2);
    cudaEventRecord(evJoin, s2);

    k_ctx_fused<<<B, 512, SMEM_CTX>>>(obs, sc, benc, Wstat, Wr, br, phase);

    cudaStreamWaitEvent(0, evJoin, 0);

    k_base  <<<dim3(NE, 16, 16), 256, SMEM_BASE>>>(b1);
    k_expert<<<2*NPAIR, 128, SMEM_EXP>>>(fut, eps, t, b2, b1);
    k_final <<<FIN_BLKS, 256>>>((float*)d_out);
}

// round 16
// speedup vs baseline: 1.5669x; 1.0141x over previous
#include <cuda_runtime.h>
#include <cuda_bf16.h>
#include <math.h>

#define B   512
#define TP  256
#define DM  512
#define DS  32
#define NE  6
#define NPAIR 532

// ---------------- device scratch ----------------
__device__ float g_ab[1000];
__device__ float g_gctx[B*DM];
__device__ float g_temb[B*DM];
__device__ float g_probs[B*NE];
__device__ int   g_sel[B];
__device__ float g_loss[B];
__device__ float g_outsub[NE*4*64*64];
__device__ int   g_cnt[NE];
__device__ int   g_list[NE*512];
__device__ float g_base[NE*B*512];
// fragment-tiled bf16 weights: each n8 x k16 tile contiguous as [r(8)][kk(16)] = 128 elems
__device__ __nv_bfloat16 c_Wenc[DM*64];                 // [ng 64][kg 4][128]
__device__ __nv_bfloat16 c_W1n[NE*512*64];              // [e][hg 64][kg 4][128]
__device__ __nv_bfloat16 c_W1b[(size_t)NE*512*1024];    // [e][hg 64][kg 64][128]
__device__ __nv_bfloat16 c_W2t[NE*64*512];              // [e][fg 8][kg 32][128]
__device__ float g_accL, g_accC, g_accS;
__device__ float g_psumE[NE];
__device__ float g_cntF[NE];
__device__ unsigned g_finDone;

// lean gelu: u = x*(c1 + c1*c2*s), y = 0.5x + 0.5x*tanh(u)  (5 ops + 1 MUFU)
__device__ __forceinline__ float gelu_fast(float x){
    float s = x*x;
    float t = fmaf(s, 0.035677408136f, 0.7978845608f);   // c1*c2, c1
    float u = x*t;
    float th;
    asm("tanh.approx.f32 %0, %1;" : "=f"(th) : "f"(u));
    float hx = 0.5f*x;
    return fmaf(hx, th, hx);
}

__device__ __forceinline__ void mma16816(float* c, const unsigned* a, unsigned b0, unsigned b1){
    asm("mma.sync.aligned.m16n8k16.row.col.f32.bf16.bf16.f32 "
        "{%0,%1,%2,%3}, {%4,%5,%6,%7}, {%8,%9}, {%0,%1,%2,%3};"
        : "+f"(c[0]), "+f"(c[1]), "+f"(c[2]), "+f"(c[3])
        : "r"(a[0]), "r"(a[1]), "r"(a[2]), "r"(a[3]), "r"(b0), "r"(b1));
}

// ---------------- K0: init scalars + Wenc convert (tiled) ----------------
__global__ void k_init2(const float* __restrict__ Wenc){
    int tid = threadIdx.x;
    if (blockIdx.x == 0){
        if (tid < NE){ g_cnt[tid] = 0; g_psumE[tid] = 0.0f; g_cntF[tid] = 0.0f; }
        if (tid == 6){ g_accL = 0.0f; g_accC = 0.0f; g_accS = 0.0f; g_finDone = 0u; }
        g_loss[tid] = 0.0f;
        g_loss[tid + 256] = 0.0f;
        if (tid == 0){
            float ab = 1.0f;
            const float step = (0.02f - 0.0001f) / 999.0f;
            for (int i = 0; i < 1000; i++){
                float beta = 0.0001f + step * (float)i;
                ab *= (1.0f - beta);
                g_ab[i] = ab;
            }
        }
    } else {
        int gid = (blockIdx.x - 1)*256 + tid;   // 1024 threads
        int n = gid >> 1, kh = (gid & 1) * 32;
        int ng = n >> 3, r = n & 7;
        #pragma unroll
        for (int i = 0; i < 32; i++){
            int k = kh + i;
            int kg = k >> 4, kk = k & 15;
            c_Wenc[(ng*4 + kg)*128 + r*16 + kk] = __float2bfloat16_rn(Wenc[k*DM + n]);
        }
    }
}

// ---------------- K1: merged prep (W1, W2 converts + temb + g_base zero) ----------------
__global__ void k_prep(const int* __restrict__ t,
                       const float* __restrict__ W1, const float* __restrict__ W2){
    __shared__ float sm[32][33];
    int bid = blockIdx.x;
    int tid = threadIdx.x;

    if (bid < 3264){                       // W1 convert
        int e = bid / 544, rem = bid - e*544;
        int kt = rem >> 4, ht = rem & 15;
        int i = tid >> 3, j4 = (tid & 7) * 4;
        float4 v = *(const float4*)&W1[((size_t)e*1088 + kt*32 + i)*512 + ht*32 + j4];
        sm[i][j4] = v.x; sm[i][j4+1] = v.y; sm[i][j4+2] = v.z; sm[i][j4+3] = v.w;
        __syncthreads();
        int h = ht*32 + i;
        int k = kt*32 + j4;
        __nv_bfloat162 p0 = __floats2bfloat162_rn(sm[j4][i],   sm[j4+1][i]);
        __nv_bfloat162 p1 = __floats2bfloat162_rn(sm[j4+2][i], sm[j4+3][i]);
        int hg = h >> 3, r = h & 7;
        __nv_bfloat16* dst;
        if (kt < 2){
            int kg = k >> 4, kk = k & 15;
            dst = c_W1n + (size_t)e*32768 + (hg*4 + kg)*128 + r*16 + kk;
        } else {
            int kp = k - 64;
            int kg = kp >> 4, kk = kp & 15;
            dst = c_W1b + (size_t)e*524288 + (size_t)(hg*64 + kg)*128 + r*16 + kk;
        }
        *(__nv_bfloat162*)dst       = p0;
        *(__nv_bfloat162*)(dst + 2) = p1;
    } else if (bid < 3456){                // W2 convert
        int idx2 = bid - 3264;
        int e = idx2 >> 5, rem = idx2 & 31;
        int ht = rem >> 1, ft = rem & 1;
        int i = tid >> 3, j4 = (tid & 7) * 4;
        float4 v = *(const float4*)&W2[((size_t)e*512 + ht*32 + i)*64 + ft*32 + j4];
        sm[i][j4] = v.x; sm[i][j4+1] = v.y; sm[i][j4+2] = v.z; sm[i][j4+3] = v.w;
        __syncthreads();
        int f = ft*32 + i;
        int h = ht*32 + j4;
        __nv_bfloat162 p0 = __floats2bfloat162_rn(sm[j4][i],   sm[j4+1][i]);
        __nv_bfloat162 p1 = __floats2bfloat162_rn(sm[j4+2][i], sm[j4+3][i]);
        int fg = f >> 3, r = f & 7;
        int kg = h >> 4, kk = h & 15;
        __nv_bfloat16* dst = c_W2t + (size_t)e*32768 + (fg*32 + kg)*128 + r*16 + kk;
        *(__nv_bfloat162*)dst       = p0;
        *(__nv_bfloat162*)(dst + 2) = p1;
    } else if (bid < 3968){                // temb
        int b = bid - 3456;
        float tv = (float)t[b];
        for (int j = tid; j < DM; j += 256){
            int i = (j < 256) ? j : (j - 256);
            float freq = expf(-9.210340371976184f * (float)i / 256.0f);
            float a = tv * freq;
            g_temb[b*DM + j] = (j < 256) ? sinf(a) : cosf(a);
        }
    } else {                               // zero g_base
        int zb = bid - 3968;
        float4* p = (float4*)g_base;
        const int total4 = NE*B*512/4;     // 393216
        for (int i = zb*256 + tid; i < total4; i += 64*256){
            float4 z; z.x = 0.0f; z.y = 0.0f; z.z = 0.0f; z.w = 0.0f;
            p[i] = z;
        }
    }
}

// ---------------- K2: fused ctx GEMM + router ----------------
#define APAD 72
__global__ void __launch_bounds__(512, 1)
k_ctx_fused(const float* __restrict__ obs, const float* __restrict__ sc,
            const float* __restrict__ benc, const float* __restrict__ Wstat,
            const float* __restrict__ Wr, const float* __restrict__ br,
            const int* __restrict__ phase){
    extern __shared__ char smraw[];
    __nv_bfloat16* As = (__nv_bfloat16*)smraw;
    float* pre  = (float*)(As + 256*APAD);
    float* gbuf = pre + 512;

    int b = blockIdx.x;
    int tid = threadIdx.x;

    {
        int row = tid >> 1;
        int c0  = (tid & 1) * 32;
        const float4* src = (const float4*)(obs + (size_t)b*TP*64 + row*64 + c0);
        __nv_bfloat16* arow = As + row*APAD + c0;
        #pragma unroll
        for (int i = 0; i < 8; i++){
            float4 v = src[i];
            *(__nv_bfloat162*)(arow + i*4    ) = __floats2bfloat162_rn(v.x, v.y);
            *(__nv_bfloat162*)(arow + i*4 + 2) = __floats2bfloat162_rn(v.z, v.w);
        }
    }
    {
        float acc = benc[tid];
        #pragma unroll
        for (int k = 0; k < 32; k++) acc = fmaf(sc[b*DS + k], Wstat[k*DM + tid], acc);
        pre[tid] = acc;
    }
    __syncthreads();

    int warp = tid >> 5, lane = tid & 31;
    int qrow = lane >> 2, qk2 = (lane & 3) * 2;
    int n0 = warp * 32;

    unsigned bfr[4][4][2];
    #pragma unroll
    for (int nt = 0; nt < 4; nt++)
        #pragma unroll
        for (int ks = 0; ks < 4; ks++){
            const __nv_bfloat16* bp = c_Wenc + ((warp*4 + nt)*4 + ks)*128 + qrow*16 + qk2;
            bfr[nt][ks][0] = *(const unsigned*)(bp);
            bfr[nt][ks][1] = *(const unsigned*)(bp + 8);
        }
    float prev[4][2];
    #pragma unroll
    for (int nt = 0; nt < 4; nt++){
        prev[nt][0] = pre[n0 + nt*8 + qk2];
        prev[nt][1] = pre[n0 + nt*8 + qk2 + 1];
    }

    float s[4][2];
    #pragma unroll
    for (int nt = 0; nt < 4; nt++){ s[nt][0] = 0.0f; s[nt][1] = 0.0f; }

    #pragma unroll 2
    for (int mc = 0; mc < 8; mc++){
        unsigned a[2][4][4];
        #pragma unroll
        for (int mt = 0; mt < 2; mt++)
            #pragma unroll
            for (int ks = 0; ks < 4; ks++){
                const __nv_bfloat16* ap = As + (mc*32 + mt*16 + qrow)*APAD + ks*16 + qk2;
                a[mt][ks][0] = *(const unsigned*)(ap);
                a[mt][ks][1] = *(const unsigned*)(ap + 8*APAD);
                a[mt][ks][2] = *(const unsigned*)(ap + 8);
                a[mt][ks][3] = *(const unsigned*)(ap + 8*APAD + 8);
            }
        float c[2][4][4];
        #pragma unroll
        for (int mt = 0; mt < 2; mt++)
            #pragma unroll
            for (int nt = 0; nt < 4; nt++){
                c[mt][nt][0] = prev[nt][0];   // bias pre-loaded into accumulator
                c[mt][nt][1] = prev[nt][1];
                c[mt][nt][2] = prev[nt][0];
                c[mt][nt][3] = prev[nt][1];
            }
        #pragma unroll
        for (int ks = 0; ks < 4; ks++)
            #pragma unroll
            for (int mt = 0; mt < 2; mt++)
                #pragma unroll
                for (int nt = 0; nt < 4; nt++)
                    mma16816(c[mt][nt], a[mt][ks], bfr[nt][ks][0], bfr[nt][ks][1]);
        #pragma unroll
        for (int mt = 0; mt < 2; mt++)
            #pragma unroll
            for (int nt = 0; nt < 4; nt++){
                s[nt][0] += gelu_fast(c[mt][nt][0]) + gelu_fast(c[mt][nt][2]);
                s[nt][1] += gelu_fast(c[mt][nt][1]) + gelu_fast(c[mt][nt][3]);
            }
    }

    #pragma unroll
    for (int off = 16; off >= 4; off >>= 1)
        #pragma unroll
        for (int nt = 0; nt < 4; nt++){
            s[nt][0] += __shfl_xor_sync(0xffffffff, s[nt][0], off);
            s[nt][1] += __shfl_xor_sync(0xffffffff, s[nt][1], off);
        }
    if (qrow == 0){
        #pragma unroll
        for (int nt = 0; nt < 4; nt++){
            int j = n0 + nt*8 + qk2;
            float v0 = s[nt][0] * (1.0f/256.0f);
            float v1 = s[nt][1] * (1.0f/256.0f);
            gbuf[j] = v0; gbuf[j+1] = v1;
            g_gctx[b*DM + j]     = v0;
            g_gctx[b*DM + j + 1] = v1;
        }
    }
    __syncthreads();

    if (warp == 0){
        float p[6] = {0,0,0,0,0,0};
        for (int k = lane; k < DM; k += 32){
            float g = gbuf[k];
            const float* w = Wr + k*NE;
            #pragma unroll
            for (int e = 0; e < 6; e++) p[e] = fmaf(g, w[e], p[e]);
        }
        #pragma unroll
        for (int off = 16; off; off >>= 1)
            #pragma unroll
            for (int e = 0; e < 6; e++) p[e] += __shfl_xor_sync(0xffffffff, p[e], off);
        if (lane == 0){
            float l[6], pr[6];
            #pragma unroll
            for (int e = 0; e < 6; e++) l[e] = p[e] + br[e];
            float m = l[0];
            #pragma unroll
            for (int e = 1; e < 6; e++) m = fmaxf(m, l[e]);
            float sv = 0.0f;
            #pragma unroll
            for (int e = 0; e < 6; e++){ pr[e] = expf(l[e] - m); sv += pr[e]; }
            float inv = 1.0f / sv;
            #pragma unroll
            for (int e = 0; e < 6; e++){ pr[e] *= inv; g_probs[b*NE + e] = pr[e]; }
            int pl = phase[b];
            int sel = pl + ((pr[pl+3] > pr[pl]) ? 3 : 0);
            g_sel[b] = sel;
            if (b < 4){
                #pragma unroll
                for (int e = 0; e < 6; e++){
                    int idx = atomicAdd(&g_cnt[e], 1);
                    g_list[e*512 + idx] = b;
                }
            } else {
                int idx = atomicAdd(&g_cnt[sel], 1);
                g_list[sel*512 + idx] = b;
            }
        }
    }
}

// ---------------- K3c: base via bf16 MMA, k-split x8 (z=16), atomic accumulate ----------------
#define BAPAD 136
__global__ void __launch_bounds__(256, 2)
k_base(const float* __restrict__ b1_unused){
    extern __shared__ char smraw[];
    __nv_bfloat16* As = (__nv_bfloat16*)smraw;   // 32 x 136 (128 k-cols + pad)
    int* bl = (int*)(As + 32*BAPAD);             // 32

    int e = blockIdx.x, tile = blockIdx.y;
    int hs = blockIdx.z & 1;       // h-half: 256 cols each
    int kq = blockIdx.z >> 1;      // k-chunk: 0..7 (128 k each)
    int n = g_cnt[e], s0 = tile*32;
    if (s0 >= n) return;
    int tid = threadIdx.x;

    if (tid < 32){
        int s = s0 + tid;
        bl[tid] = (s < n) ? g_list[e*512 + s] : g_list[e*512];
    }
    __syncthreads();

    {   // load 32 rows x 128 cols of (gctx|temb) k-chunk
        int r = tid >> 3, seg = tid & 7;   // seg: 16-col group
        int bb = bl[r];
        const float* srcbase = (kq < 4)
            ? (g_gctx + bb*512 + kq*128)
            : (g_temb + bb*512 + (kq - 4)*128);
        const float4* src = (const float4*)(srcbase + seg*16);
        __nv_bfloat16* dst = As + r*BAPAD + seg*16;
        #pragma unroll
        for (int i = 0; i < 4; i++){
            float4 v = src[i];
            *(__nv_bfloat162*)(dst + i*4    ) = __floats2bfloat162_rn(v.x, v.y);
            *(__nv_bfloat162*)(dst + i*4 + 2) = __floats2bfloat162_rn(v.z, v.w);
        }
    }
    __syncthreads();

    int warp = tid >> 5, lane = tid & 31;
    int qrow = lane >> 2;
    int qk2 = (lane & 3) * 2;
    int nb = hs*256 + warp*32;
    int hg0 = nb >> 3;
    const __nv_bfloat16* W1bE = c_W1b + (size_t)e*524288;

    float acc[2][4][4];
    #pragma unroll
    for (int mt = 0; mt < 2; mt++)
        #pragma unroll
        for (int nt = 0; nt < 4; nt++)
            #pragma unroll
            for (int r = 0; r < 4; r++) acc[mt][nt][r] = 0.0f;

    #pragma unroll
    for (int kc = 0; kc < 2; kc++){
        #pragma unroll
        for (int ks = 0; ks < 4; ks++){
            int kof = kc*64 + ks*16 + qk2;
            int kg = kq*8 + kc*4 + ks;
            unsigned a[2][4];
            #pragma unroll
            for (int mt = 0; mt < 2; mt++){
                const __nv_bfloat16* ap = As + (mt*16 + qrow)*BAPAD + kof;
                a[mt][0] = *(const unsigned*)(ap);
                a[mt][1] = *(const unsigned*)(ap + 8*BAPAD);
                a[mt][2] = *(const unsigned*)(ap + 8);
                a[mt][3] = *(const unsigned*)(ap + 8*BAPAD + 8);
            }
            #pragma unroll
            for (int nt = 0; nt < 4; nt++){
                const __nv_bfloat16* bp = W1bE + (size_t)((hg0 + nt)*64 + kg)*128 + qrow*16 + qk2;
                unsigned b0 = *(const unsigned*)(bp);
                unsigned b1v = *(const unsigned*)(bp + 8);
                mma16816(acc[0][nt], a[0], b0, b1v);
                mma16816(acc[1][nt], a[1], b0, b1v);
            }
        }
    }

    #pragma unroll
    for (int mt = 0; mt < 2; mt++){
        #pragma unroll
        for (int half = 0; half < 2; half++){
            int r = mt*16 + qrow + half*8;
            if (s0 + r < n){
                int bb = bl[r];
                float* dst = g_base + ((size_t)e*B + bb)*512;
                #pragma unroll
                for (int nt = 0; nt < 4; nt++){
                    int h = nb + nt*8 + qk2;
                    atomicAdd(&dst[h],     acc[mt][nt][half*2    ]);
                    atomicAdd(&dst[h + 1], acc[mt][nt][half*2 + 1]);
                }
            }
        }
    }
}

// ---------------- K4: expert MLP ----------------
__global__ void __launch_bounds__(128, 5)
k_expert(const float* __restrict__ fut, const float* __restrict__ eps,
         const int* __restrict__ t, const float* __restrict__ b2,
         const float* __restrict__ b1){
    extern __shared__ char smraw[];
    __nv_bfloat16* nzs = (__nv_bfloat16*)smraw;       // 32 x 72
    __nv_bfloat16* hss = nzs + 32*72;                 // 32 x 520
    float* basev = (float*)(hss + 32*520);            // 512
    __shared__ float red[4];

    int p2 = blockIdx.x;
    int p = p2 >> 1, mhalf = p2 & 1;
    int b, e;
    if (p < 24){ b = p / 6; e = p - b*6; }
    else       { b = p - 20; e = g_sel[p - 20]; }
    int tid = threadIdx.x;
    bool do_loss  = (e == g_sel[b]);
    bool do_store = (b < 4);

    float ab = g_ab[t[b]];
    float sa = sqrtf(ab), sb = sqrtf(1.0f - ab);

    {
        int r = tid >> 2, c0 = (tid & 3) * 16;
        int gr = mhalf*32 + r;
        const float4* f4 = (const float4*)(fut + (size_t)b*4096 + gr*64 + c0);
        const float4* e4 = (const float4*)(eps + (size_t)b*4096 + gr*64 + c0);
        __nv_bfloat16* dst = nzs + r*72 + c0;
        #pragma unroll
        for (int i = 0; i < 4; i++){
            float4 vf = f4[i], ve = e4[i];
            *(__nv_bfloat162*)(dst + i*4    ) = __floats2bfloat162_rn(fmaf(sa,vf.x,sb*ve.x), fmaf(sa,vf.y,sb*ve.y));
            *(__nv_bfloat162*)(dst + i*4 + 2) = __floats2bfloat162_rn(fmaf(sa,vf.z,sb*ve.z), fmaf(sa,vf.w,sb*ve.w));
        }
    }
    #pragma unroll
    for (int i = 0; i < 4; i++){
        int idx = tid + i*128;
        basev[idx] = g_base[((size_t)e*B + b)*512 + idx] + b1[e*512 + idx];
    }
    __syncthreads();

    int warp = tid >> 5, lane = tid & 31;
    int qrow = lane >> 2, qk2 = (lane & 3) * 2;

    // ---- phase1: warp owns 128 h-cols, M=32 local ----
    {
        int n0 = warp * 128;
        const __nv_bfloat16* W1nE = c_W1n + (size_t)e*32768;

        unsigned a[2][4][4];
        #pragma unroll
        for (int mt = 0; mt < 2; mt++)
            #pragma unroll
            for (int ks = 0; ks < 4; ks++){
                const __nv_bfloat16* ap = nzs + (mt*16 + qrow)*72 + ks*16 + qk2;
                a[mt][ks][0] = *(const unsigned*)(ap);
                a[mt][ks][1] = *(const unsigned*)(ap + 8*72);
                a[mt][ks][2] = *(const unsigned*)(ap + 8);
                a[mt][ks][3] = *(const unsigned*)(ap + 8*72 + 8);
            }

        #pragma unroll 4
        for (int nto = 0; nto < 16; nto++){
            int h8 = n0 + nto*8;
            int hg = warp*16 + nto;
            unsigned bfr[4][2];
            #pragma unroll
            for (int ks = 0; ks < 4; ks++){
                const __nv_bfloat16* bp = W1nE + (hg*4 + ks)*128 + qrow*16 + qk2;
                bfr[ks][0] = *(const unsigned*)(bp);
                bfr[ks][1] = *(const unsigned*)(bp + 8);
            }
            int h = h8 + qk2;
            float ba0 = basev[h], ba1 = basev[h+1];
            float c0v[2][4];
            #pragma unroll
            for (int mt = 0; mt < 2; mt++){
                c0v[mt][0] = ba0; c0v[mt][1] = ba1;   // bias pre-loaded
                c0v[mt][2] = ba0; c0v[mt][3] = ba1;
            }
            #pragma unroll
            for (int ks = 0; ks < 4; ks++){
                #pragma unroll
                for (int mt = 0; mt < 2; mt++)
                    mma16816(c0v[mt], a[mt][ks], bfr[ks][0], bfr[ks][1]);
            }
            #pragma unroll
            for (int mt = 0; mt < 2; mt++){
                int r = mt*16 + qrow;
                *(__nv_bfloat162*)(hss + r*520 + h) =
                    __floats2bfloat162_rn(gelu_fast(c0v[mt][0]), gelu_fast(c0v[mt][1]));
                *(__nv_bfloat162*)(hss + (r+8)*520 + h) =
                    __floats2bfloat162_rn(gelu_fast(c0v[mt][2]), gelu_fast(c0v[mt][3]));
            }
        }
    }
    __syncthreads();

    // ---- phase2: warp owns 16 f-cols, M=32 local, K=512 ----
    int f0 = warp * 16;
    const __nv_bfloat16* W2tE = c_W2t + (size_t)e*32768;

    float acc[2][2][4];
    #pragma unroll
    for (int nt = 0; nt < 2; nt++){
        int fcol = f0 + nt*8 + qk2;
        float bb0 = b2[e*64 + fcol], bb1 = b2[e*64 + fcol + 1];
        #pragma unroll
        for (int mt = 0; mt < 2; mt++){
            acc[mt][nt][0] = bb0; acc[mt][nt][1] = bb1;   // bias pre-loaded
            acc[mt][nt][2] = bb0; acc[mt][nt][3] = bb1;
        }
    }

    #pragma unroll 8
    for (int ks = 0; ks < 32; ks++){
        unsigned bfr[2][2];
        #pragma unroll
        for (int nt = 0; nt < 2; nt++){
            int fg = warp*2 + nt;
            const __nv_bfloat16* bp = W2tE + (fg*32 + ks)*128 + qrow*16 + qk2;
            bfr[nt][0] = *(const unsigned*)(bp);
            bfr[nt][1] = *(const unsigned*)(bp + 8);
        }
        #pragma unroll
        for (int mt = 0; mt < 2; mt++){
            const __nv_bfloat16* ap = hss + (mt*16 + qrow)*520 + ks*16 + qk2;
            unsigned a2[4];
            a2[0] = *(const unsigned*)(ap);
            a2[1] = *(const unsigned*)(ap + 8*520);
            a2[2] = *(const unsigned*)(ap + 8);
            a2[3] = *(const unsigned*)(ap + 8*520 + 8);
            mma16816(acc[mt][0], a2, bfr[0][0], bfr[0][1]);
            mma16816(acc[mt][1], a2, bfr[1][0], bfr[1][1]);
        }
    }

    float lsum = 0.0f;
    #pragma unroll
    for (int mt = 0; mt < 2; mt++){
        #pragma unroll
        for (int nt = 0; nt < 2; nt++){
            int fcol = f0 + nt*8 + qk2;
            #pragma unroll
            for (int h2 = 0; h2 < 2; h2++){
                int rg = mhalf*32 + mt*16 + qrow + h2*8;
                float o0 = acc[mt][nt][h2*2    ];
                float o1 = acc[mt][nt][h2*2 + 1];
                if (do_store){
                    float2 st; st.x = o0; st.y = o1;
                    *(float2*)&g_outsub[((e*4 + b)*64 + rg)*64 + fcol] = st;
                }
                if (do_loss){
                    float2 ev = *(const float2*)&eps[(size_t)b*4096 + rg*64 + fcol];
                    float d0 = o0 - ev.x, d1 = o1 - ev.y;
                    lsum += d0*d0 + d1*d1;
                }
            }
        }
    }

    if (do_loss){
        #pragma unroll
        for (int off = 16; off; off >>= 1) lsum += __shfl_xor_sync(0xffffffff, lsum, off);
        if (lane == 0) red[warp] = lsum;
        __syncthreads();
        if (tid == 0){
            float tot = red[0] + red[1] + red[2] + red[3];
            atomicAdd(&g_loss[b], tot * (1.0f/4096.0f));
        }
    }
}

// ---------------- K5: parallel final reduction + last-block scalar ----------------
#define FIN_BLKS 96
__global__ void k_final(float* __restrict__ out){
    int bid = blockIdx.x, tid = threadIdx.x;
    if (bid < 2){
        __shared__ float sh[13];
        if (tid < 13) sh[tid] = 0.0f;
        __syncthreads();
        const float PW[3] = {1.0f, 5.0f, 5.0f};
        int b = bid*256 + tid;
        int s = g_sel[b];
        atomicAdd(&sh[0], g_loss[b] * PW[s % 3]);
        atomicAdd(&sh[1 + s], 1.0f);
        #pragma unroll
        for (int e = 0; e < 6; e++) atomicAdd(&sh[7 + e], g_probs[b*NE + e]);
        __syncthreads();
        if (tid == 0) atomicAdd(&g_accL, sh[0]);
        if (tid < 6){
            atomicAdd(&g_cntF[tid],  sh[1 + tid]);
            atomicAdd(&g_psumE[tid], sh[7 + tid]);
        }
    } else {
        int nb = FIN_BLKS - 2;
        int idx0 = (bid - 2)*256 + tid;
        int stride = nb*256;
        const int pa[7] = {0,1,3,4,0,1,2};
        const int pb[7] = {1,2,4,5,3,4,5};
        float ch = 0.0f;
        for (int i = idx0; i < 16384; i += stride){
            #pragma unroll
            for (int q = 0; q < 7; q++){
                float d = g_outsub[pa[q]*16384 + i] - g_outsub[pb[q]*16384 + i];
                ch += d*d;
            }
        }
        float smv = 0.0f;
        for (int i = idx0; i < 96768; i += stride){
            int e  = i / 16128; int r  = i - e*16128;
            int s  = r / 4032;  int r2 = r - s*4032;
            int idx = (e*4 + s)*4096 + r2;
            float d = g_outsub[idx + 64] - g_outsub[idx];
            smv += d*d;
        }
        #pragma unroll
        for (int off = 16; off; off >>= 1){
            ch  += __shfl_xor_sync(0xffffffff, ch,  off);
            smv += __shfl_xor_sync(0xffffffff, smv, off);
        }
        if ((tid & 31) == 0){
            atomicAdd(&g_accC, ch);
            atomicAdd(&g_accS, smv);
        }
    }

    __syncthreads();
    __shared__ bool amLast;
    if (tid == 0){
        __threadfence();
        unsigned old = atomicAdd(&g_finDone, 1u);
        amLast = (old == FIN_BLKS - 1);
    }
    __syncthreads();
    if (amLast && tid == 0){
        __threadfence();
        float lb = 0.0f;
        #pragma unroll
        for (int e = 0; e < 6; e++)
            lb += (g_cntF[e] / 512.0f) * (g_psumE[e] / 512.0f);
        out[0] = g_accL / 512.0f
               + 0.01f * (g_accC / 16384.0f + 0.5f * g_accS / 16128.0f)
               + 0.06f * lb;
    }
}

// ---------------- launch ----------------
extern "C" void kernel_launch(void* const* d_in, const int* in_sizes, int n_in,
                              void* d_out, int out_size){
    const float* obs  = (const float*)d_in[0];
    const float* fut  = (const float*)d_in[1];
    const float* sc   = (const float*)d_in[2];
    const float* eps  = (const float*)d_in[3];
    const int*   phase= (const int*)  d_in[4];
    const int*   t    = (const int*)  d_in[5];
    const float* Wenc = (const float*)d_in[6];
    const float* benc = (const float*)d_in[7];
    const float* Wstat= (const float*)d_in[8];
    const float* Wr   = (const float*)d_in[9];
    const float* br   = (const float*)d_in[10];
    const float* W1   = (const float*)d_in[11];
    const float* b1   = (const float*)d_in[12];
    const float* W2   = (const float*)d_in[13];
    const float* b2   = (const float*)d_in[14];

    const int SMEM_CTX  = 256*APAD*2 + 2*512*4;            // 40,960 B
    const int SMEM_BASE = 32*BAPAD*2 + 128;                // 8,832 B
    const int SMEM_EXP  = (32*72 + 32*520)*2 + 512*4;      // 39,936 B

    static bool once = false;
    static cudaStream_t s2;
    static cudaEvent_t evFork, evJoin;
    if (!once){
        cudaFuncSetAttribute(k_ctx_fused, cudaFuncAttributeMaxDynamicSharedMemorySize, SMEM_CTX);
        cudaFuncSetAttribute(k_base,      cudaFuncAttributeMaxDynamicSharedMemorySize, SMEM_BASE);
        cudaFuncSetAttribute(k_expert,    cudaFuncAttributeMaxDynamicSharedMemorySize, SMEM_EXP);
        cudaStreamCreateWithFlags(&s2, cudaStreamNonBlocking);
        cudaEventCreateWithFlags(&evFork, cudaEventDisableTiming);
        cudaEventCreateWithFlags(&evJoin, cudaEventDisableTiming);
        once = true;
    }

    k_init2<<<5, 256>>>(Wenc);

    cudaEventRecord(evFork, 0);
    cudaStreamWaitEvent(s2, evFork, 0);
    k_prep<<<4032, 256, 0, s2>>>(t, W1, W2);
    cudaEventRecord(evJoin, s2);

    k_ctx_fused<<<B, 512, SMEM_CTX>>>(obs, sc, benc, Wstat, Wr, br, phase);

    cudaStreamWaitEvent(0, evJoin, 0);

    k_base  <<<dim3(NE, 16, 16), 256, SMEM_BASE>>>(b1);
    k_expert<<<2*NPAIR, 128, SMEM_EXP>>>(fut, eps, t, b2, b1);
    k_final <<<FIN_BLKS, 256>>>((float*)d_out);
}